// round 1
// baseline (speedup 1.0000x reference)
#include <cuda_runtime.h>
#include <math.h>

// Problem constants
#define MROWS  4096      // B*T
#define DMODEL 1024
#define D3     3072
#define DFF    4096
#define TSEQ   2048
#define NHEAD  16
#define DHEAD  64

// ---------------- scratch (device globals: no runtime allocation) ----------
__device__ float g_xln[(size_t)MROWS * DMODEL];
__device__ float g_qkv[(size_t)MROWS * D3];
__device__ float g_y  [(size_t)MROWS * DMODEL];
__device__ float g_x1 [(size_t)MROWS * DMODEL];
__device__ float g_h  [(size_t)MROWS * DMODEL];
__device__ float g_act[(size_t)MROWS * DFF];

// ---------------- LayerNorm: one block per row, D=1024 ---------------------
__global__ void ln_kernel(const float* __restrict__ x,
                          const float* __restrict__ w,
                          const float* __restrict__ b,
                          float* __restrict__ out) {
    int row = blockIdx.x;
    int tid = threadIdx.x;                       // 256 threads, 4 floats each
    const float* xr = x + (size_t)row * DMODEL;

    float4 v = *(const float4*)(xr + tid * 4);
    float s  = v.x + v.y + v.z + v.w;
    float ss = v.x * v.x + v.y * v.y + v.z * v.z + v.w * v.w;

    // warp reduce
    #pragma unroll
    for (int off = 16; off >= 1; off >>= 1) {
        s  += __shfl_xor_sync(0xffffffffu, s,  off);
        ss += __shfl_xor_sync(0xffffffffu, ss, off);
    }
    __shared__ float rs[8], rss[8];
    __shared__ float stats[2];
    int wid = tid >> 5, lane = tid & 31;
    if (lane == 0) { rs[wid] = s; rss[wid] = ss; }
    __syncthreads();
    if (tid == 0) {
        float S = 0.f, SS = 0.f;
        #pragma unroll
        for (int i = 0; i < 8; i++) { S += rs[i]; SS += rss[i]; }
        float mu  = S * (1.0f / DMODEL);
        float var = SS * (1.0f / DMODEL) - mu * mu;
        stats[0] = mu;
        stats[1] = rsqrtf(var + 1e-5f);
    }
    __syncthreads();
    float mu = stats[0], r = stats[1];

    float4 wv = *(const float4*)(w + tid * 4);
    float4 bv = *(const float4*)(b + tid * 4);
    float4 o;
    o.x = (v.x - mu) * r * wv.x + bv.x;
    o.y = (v.y - mu) * r * wv.y + bv.y;
    o.z = (v.z - mu) * r * wv.z + bv.z;
    o.w = (v.w - mu) * r * wv.w + bv.w;
    *(float4*)(out + (size_t)row * DMODEL + tid * 4) = o;
}

// ---------------- GEMM NT: C[M,N] = A[M,K] * B[N,K]^T + bias (+epilogue) ---
// EPI: 0 = none, 1 = exact GELU, 2 = residual add (res[M,N])
__device__ __forceinline__ float gelu_exact(float v) {
    return 0.5f * v * (1.0f + erff(v * 0.70710678118654752f));
}

template <int EPI>
__global__ void __launch_bounds__(256, 2)
gemm_nt(const float* __restrict__ A, const float* __restrict__ B,
        const float* __restrict__ bias, const float* __restrict__ res,
        float* __restrict__ C, int N, int K) {
    __shared__ __align__(16) float As[16][132];
    __shared__ __align__(16) float Bs[16][132];

    int tid = threadIdx.x;
    int bn = blockIdx.x, bm = blockIdx.y;
    int ty = tid >> 4, tx = tid & 15;

    int r  = tid >> 2;                  // 0..63
    int c4 = (tid & 3) * 4;             // 0,4,8,12
    const float* Aptr = A + (size_t)(bm * 128 + r) * K + c4;
    const float* Bptr = B + (size_t)(bn * 128 + r) * K + c4;
    const size_t strideA = (size_t)64 * K;

    float acc[8][8];
    #pragma unroll
    for (int i = 0; i < 8; i++)
        #pragma unroll
        for (int j = 0; j < 8; j++) acc[i][j] = 0.f;

    for (int k0 = 0; k0 < K; k0 += 16) {
        float4 a0 = *(const float4*)(Aptr + k0);
        float4 a1 = *(const float4*)(Aptr + strideA + k0);
        float4 b0 = *(const float4*)(Bptr + k0);
        float4 b1 = *(const float4*)(Bptr + strideA + k0);
        __syncthreads();
        As[c4 + 0][r]      = a0.x; As[c4 + 1][r]      = a0.y;
        As[c4 + 2][r]      = a0.z; As[c4 + 3][r]      = a0.w;
        As[c4 + 0][r + 64] = a1.x; As[c4 + 1][r + 64] = a1.y;
        As[c4 + 2][r + 64] = a1.z; As[c4 + 3][r + 64] = a1.w;
        Bs[c4 + 0][r]      = b0.x; Bs[c4 + 1][r]      = b0.y;
        Bs[c4 + 2][r]      = b0.z; Bs[c4 + 3][r]      = b0.w;
        Bs[c4 + 0][r + 64] = b1.x; Bs[c4 + 1][r + 64] = b1.y;
        Bs[c4 + 2][r + 64] = b1.z; Bs[c4 + 3][r + 64] = b1.w;
        __syncthreads();

        #pragma unroll
        for (int k = 0; k < 16; k++) {
            float a[8], bb[8];
            *(float4*)&a[0]  = *(const float4*)&As[k][ty * 8];
            *(float4*)&a[4]  = *(const float4*)&As[k][ty * 8 + 4];
            *(float4*)&bb[0] = *(const float4*)&Bs[k][tx * 8];
            *(float4*)&bb[4] = *(const float4*)&Bs[k][tx * 8 + 4];
            #pragma unroll
            for (int i = 0; i < 8; i++)
                #pragma unroll
                for (int j = 0; j < 8; j++)
                    acc[i][j] = fmaf(a[i], bb[j], acc[i][j]);
        }
    }

    int m0 = bm * 128 + ty * 8;
    int n0 = bn * 128 + tx * 8;
    float bvals[8];
    *(float4*)&bvals[0] = *(const float4*)(bias + n0);
    *(float4*)&bvals[4] = *(const float4*)(bias + n0 + 4);

    #pragma unroll
    for (int i = 0; i < 8; i++) {
        float v[8];
        #pragma unroll
        for (int j = 0; j < 8; j++) {
            float t = acc[i][j] + bvals[j];
            if (EPI == 1) t = gelu_exact(t);
            v[j] = t;
        }
        size_t off = (size_t)(m0 + i) * N + n0;
        if (EPI == 2) {
            float4 r0 = *(const float4*)(res + off);
            float4 r1 = *(const float4*)(res + off + 4);
            v[0] += r0.x; v[1] += r0.y; v[2] += r0.z; v[3] += r0.w;
            v[4] += r1.x; v[5] += r1.y; v[6] += r1.z; v[7] += r1.w;
        }
        *(float4*)(C + off)     = make_float4(v[0], v[1], v[2], v[3]);
        *(float4*)(C + off + 4) = make_float4(v[4], v[5], v[6], v[7]);
    }
}

// ---------------- Causal flash attention, fp32 -----------------------------
// grid: (T/64, H, B), block 256. 64 queries/CTA, key blocks of 64, DH=64.
#define AT_PAD 68
#define ATT_SMEM (4 * 64 * AT_PAD * 4)

__global__ void __launch_bounds__(256, 3)
attn_kernel(const float* __restrict__ qkv, float* __restrict__ y) {
    extern __shared__ __align__(16) float sm[];
    float* Qs = sm;
    float* Ks = Qs + 64 * AT_PAD;
    float* Vs = Ks + 64 * AT_PAD;
    float* Ps = Vs + 64 * AT_PAD;

    int qb = blockIdx.x, h = blockIdx.y, b = blockIdx.z;
    int tid = threadIdx.x;
    int ty = tid >> 4, tx = tid & 15;
    size_t base = (size_t)b * TSEQ * D3;
    int hoff = h * DHEAD;

    // load Q tile [64 x 64]
    #pragma unroll
    for (int i = 0; i < 4; i++) {
        int v = tid + i * 256;
        int rr = v >> 4;
        int cc = (v & 15) * 4;
        *(float4*)&Qs[rr * AT_PAD + cc] =
            *(const float4*)(qkv + base + (size_t)(qb * 64 + rr) * D3 + hoff + cc);
    }

    float m_i[4], l_i[4], o[4][4];
    #pragma unroll
    for (int i = 0; i < 4; i++) {
        m_i[i] = -INFINITY; l_i[i] = 0.f;
        #pragma unroll
        for (int j = 0; j < 4; j++) o[i][j] = 0.f;
    }

    for (int kb = 0; kb <= qb; kb++) {
        __syncthreads();   // protect Ks/Vs/Ps reuse (also publishes Qs on iter 0)
        #pragma unroll
        for (int i = 0; i < 4; i++) {
            int v = tid + i * 256;
            int rr = v >> 4;
            int cc = (v & 15) * 4;
            size_t rowb = base + (size_t)(kb * 64 + rr) * D3 + hoff;
            *(float4*)&Ks[rr * AT_PAD + cc] = *(const float4*)(qkv + rowb + 1024 + cc);
            *(float4*)&Vs[rr * AT_PAD + cc] = *(const float4*)(qkv + rowb + 2048 + cc);
        }
        __syncthreads();

        // S = Q K^T  (4x4 micro-tile per thread)
        float s[4][4];
        #pragma unroll
        for (int i = 0; i < 4; i++)
            #pragma unroll
            for (int j = 0; j < 4; j++) s[i][j] = 0.f;

        for (int d = 0; d < DHEAD; d += 4) {
            float4 qv[4], kv[4];
            #pragma unroll
            for (int i = 0; i < 4; i++) qv[i] = *(const float4*)&Qs[(ty * 4 + i) * AT_PAD + d];
            #pragma unroll
            for (int j = 0; j < 4; j++) kv[j] = *(const float4*)&Ks[(tx * 4 + j) * AT_PAD + d];
            #pragma unroll
            for (int i = 0; i < 4; i++)
                #pragma unroll
                for (int j = 0; j < 4; j++)
                    s[i][j] += qv[i].x * kv[j].x + qv[i].y * kv[j].y +
                               qv[i].z * kv[j].z + qv[i].w * kv[j].w;
        }

        const float sc = 0.125f;   // 1/sqrt(64)
        #pragma unroll
        for (int i = 0; i < 4; i++)
            #pragma unroll
            for (int j = 0; j < 4; j++) s[i][j] *= sc;
        if (kb == qb) {
            #pragma unroll
            for (int i = 0; i < 4; i++)
                #pragma unroll
                for (int j = 0; j < 4; j++)
                    if (tx * 4 + j > ty * 4 + i) s[i][j] = -1e30f;
        }

        // online softmax per query row (row spread across 16 lanes of a half-warp)
        #pragma unroll
        for (int i = 0; i < 4; i++) {
            float mx = fmaxf(fmaxf(s[i][0], s[i][1]), fmaxf(s[i][2], s[i][3]));
            #pragma unroll
            for (int off = 8; off >= 1; off >>= 1)
                mx = fmaxf(mx, __shfl_xor_sync(0xffffffffu, mx, off, 16));
            float mnew = fmaxf(m_i[i], mx);
            float f = __expf(m_i[i] - mnew);
            m_i[i] = mnew;
            float rsum = 0.f;
            #pragma unroll
            for (int j = 0; j < 4; j++) { s[i][j] = __expf(s[i][j] - mnew); rsum += s[i][j]; }
            #pragma unroll
            for (int off = 8; off >= 1; off >>= 1)
                rsum += __shfl_xor_sync(0xffffffffu, rsum, off, 16);
            l_i[i] = l_i[i] * f + rsum;
            #pragma unroll
            for (int j = 0; j < 4; j++) o[i][j] *= f;
            *(float4*)&Ps[(ty * 4 + i) * AT_PAD + tx * 4] =
                make_float4(s[i][0], s[i][1], s[i][2], s[i][3]);
        }
        __syncthreads();

        // O += P V
        for (int k = 0; k < 64; k += 4) {
            float4 pv[4], vv[4];
            #pragma unroll
            for (int i = 0; i < 4; i++) pv[i] = *(const float4*)&Ps[(ty * 4 + i) * AT_PAD + k];
            #pragma unroll
            for (int kk = 0; kk < 4; kk++) vv[kk] = *(const float4*)&Vs[(k + kk) * AT_PAD + tx * 4];
            #pragma unroll
            for (int i = 0; i < 4; i++) {
                float* vr0 = (float*)&vv[0];
                float* vr1 = (float*)&vv[1];
                float* vr2 = (float*)&vv[2];
                float* vr3 = (float*)&vv[3];
                #pragma unroll
                for (int j = 0; j < 4; j++)
                    o[i][j] += pv[i].x * vr0[j] + pv[i].y * vr1[j] +
                               pv[i].z * vr2[j] + pv[i].w * vr3[j];
            }
        }
    }

    #pragma unroll
    for (int i = 0; i < 4; i++) {
        float inv = 1.0f / l_i[i];
        int q = qb * 64 + ty * 4 + i;
        *(float4*)(y + (size_t)(b * TSEQ + q) * DMODEL + hoff + tx * 4) =
            make_float4(o[i][0] * inv, o[i][1] * inv, o[i][2] * inv, o[i][3] * inv);
    }
}

// ---------------- launch ---------------------------------------------------
static float* symaddr(const void* sym) {
    void* p = nullptr;
    cudaGetSymbolAddress(&p, sym);
    return (float*)p;
}

extern "C" void kernel_launch(void* const* d_in, const int* in_sizes, int n_in,
                              void* d_out, int out_size) {
    const float* x      = (const float*)d_in[0];
    const float* ln1_w  = (const float*)d_in[1];
    const float* ln1_b  = (const float*)d_in[2];
    const float* qkv_w  = (const float*)d_in[3];
    const float* qkv_b  = (const float*)d_in[4];
    const float* out_w  = (const float*)d_in[5];
    const float* out_b  = (const float*)d_in[6];
    const float* ln2_w  = (const float*)d_in[7];
    const float* ln2_b  = (const float*)d_in[8];
    const float* mlp_w1 = (const float*)d_in[9];
    const float* mlp_b1 = (const float*)d_in[10];
    const float* mlp_w2 = (const float*)d_in[11];
    const float* mlp_b2 = (const float*)d_in[12];
    float* out = (float*)d_out;

    float* xln = symaddr(g_xln);
    float* qkv = symaddr(g_qkv);
    float* y   = symaddr(g_y);
    float* x1  = symaddr(g_x1);
    float* h   = symaddr(g_h);
    float* act = symaddr(g_act);

    cudaFuncSetAttribute(attn_kernel, cudaFuncAttributeMaxDynamicSharedMemorySize, ATT_SMEM);

    // 1. LN1
    ln_kernel<<<MROWS, 256>>>(x, ln1_w, ln1_b, xln);
    // 2. QKV projection: [4096,1024] x [3072,1024]^T
    gemm_nt<0><<<dim3(D3 / 128, MROWS / 128), 256>>>(xln, qkv_w, qkv_b, nullptr, qkv, D3, DMODEL);
    // 3. causal attention
    attn_kernel<<<dim3(TSEQ / 64, NHEAD, 2), 256, ATT_SMEM>>>(qkv, y);
    // 4. out projection + residual -> x1
    gemm_nt<2><<<dim3(DMODEL / 128, MROWS / 128), 256>>>(y, out_w, out_b, x, x1, DMODEL, DMODEL);
    // 5. LN2
    ln_kernel<<<MROWS, 256>>>(x1, ln2_w, ln2_b, h);
    // 6. MLP up + exact GELU
    gemm_nt<1><<<dim3(DFF / 128, MROWS / 128), 256>>>(h, mlp_w1, mlp_b1, nullptr, act, DFF, DMODEL);
    // 7. MLP down + residual -> output
    gemm_nt<2><<<dim3(DMODEL / 128, MROWS / 128), 256>>>(act, mlp_w2, mlp_b2, x1, out, DMODEL, DFF);
}

// round 2
// speedup vs baseline: 1.2458x; 1.2458x over previous
#include <cuda_runtime.h>
#include <mma.h>
#include <math.h>

using namespace nvcuda;

// Problem constants
#define MROWS  4096      // B*T
#define DMODEL 1024
#define D3     3072
#define DFF    4096
#define TSEQ   2048
#define NHEAD  16
#define DHEAD  64

// GEMM tiling
#define BM 128
#define BN 128
#define BK 32
#define LDS_K (BK + 8)     // 40, padded
#define LDC_S 132          // epilogue smem stride
#define GEMM_SMEM (2 * (BM * LDS_K + BN * LDS_K) * 4)   // 81920 bytes

// ---------------- scratch (device globals: no runtime allocation) ----------
__device__ float g_xln[(size_t)MROWS * DMODEL];
__device__ float g_qkv[(size_t)MROWS * D3];
__device__ float g_y  [(size_t)MROWS * DMODEL];
__device__ float g_x1 [(size_t)MROWS * DMODEL];
__device__ float g_h  [(size_t)MROWS * DMODEL];
__device__ float g_act[(size_t)MROWS * DFF];

// ---------------- cp.async helpers -----------------------------------------
__device__ __forceinline__ void cp_async16(void* smem, const void* gmem) {
    unsigned s = (unsigned)__cvta_generic_to_shared(smem);
    asm volatile("cp.async.cg.shared.global [%0], [%1], 16;\n" :: "r"(s), "l"(gmem));
}
__device__ __forceinline__ void cp_commit() {
    asm volatile("cp.async.commit_group;\n");
}
template <int N>
__device__ __forceinline__ void cp_wait() {
    asm volatile("cp.async.wait_group %0;\n" :: "n"(N));
}

// ---------------- LayerNorm: one block per row, D=1024 ---------------------
__global__ void ln_kernel(const float* __restrict__ x,
                          const float* __restrict__ w,
                          const float* __restrict__ b,
                          float* __restrict__ out) {
    int row = blockIdx.x;
    int tid = threadIdx.x;                       // 256 threads, 4 floats each
    const float* xr = x + (size_t)row * DMODEL;

    float4 v = *(const float4*)(xr + tid * 4);
    float s  = v.x + v.y + v.z + v.w;
    float ss = v.x * v.x + v.y * v.y + v.z * v.z + v.w * v.w;

    #pragma unroll
    for (int off = 16; off >= 1; off >>= 1) {
        s  += __shfl_xor_sync(0xffffffffu, s,  off);
        ss += __shfl_xor_sync(0xffffffffu, ss, off);
    }
    __shared__ float rs[8], rss[8];
    __shared__ float stats[2];
    int wid = tid >> 5, lane = tid & 31;
    if (lane == 0) { rs[wid] = s; rss[wid] = ss; }
    __syncthreads();
    if (tid == 0) {
        float S = 0.f, SS = 0.f;
        #pragma unroll
        for (int i = 0; i < 8; i++) { S += rs[i]; SS += rss[i]; }
        float mu  = S * (1.0f / DMODEL);
        float var = SS * (1.0f / DMODEL) - mu * mu;
        stats[0] = mu;
        stats[1] = rsqrtf(var + 1e-5f);
    }
    __syncthreads();
    float mu = stats[0], r = stats[1];

    float4 wv = *(const float4*)(w + tid * 4);
    float4 bv = *(const float4*)(b + tid * 4);
    float4 o;
    o.x = (v.x - mu) * r * wv.x + bv.x;
    o.y = (v.y - mu) * r * wv.y + bv.y;
    o.z = (v.z - mu) * r * wv.z + bv.z;
    o.w = (v.w - mu) * r * wv.w + bv.w;
    *(float4*)(out + (size_t)row * DMODEL + tid * 4) = o;
}

// ---------------- TF32 tensor-core GEMM NT ----------------------------------
// C[M,N] = A[M,K] * B[N,K]^T + bias (+epilogue).  EPI: 0=none, 1=GELU, 2=residual
__device__ __forceinline__ float gelu_exact(float v) {
    return 0.5f * v * (1.0f + erff(v * 0.70710678118654752f));
}

template <int EPI>
__global__ void __launch_bounds__(256, 2)
gemm_tf32(const float* __restrict__ A, const float* __restrict__ B,
          const float* __restrict__ bias, const float* __restrict__ res,
          float* __restrict__ C, int N, int K) {
    extern __shared__ __align__(16) float smem[];
    float* As = smem;                         // 2 stages of [BM][LDS_K]
    float* Bs = smem + 2 * BM * LDS_K;        // 2 stages of [BN][LDS_K]

    int tid = threadIdx.x;
    int wid = tid >> 5;
    int bn = blockIdx.x, bm = blockIdx.y;
    int wm = wid >> 2;            // 0..1 : warp row (64 rows each)
    int wn = wid & 3;             // 0..3 : warp col (32 cols each)

    wmma::fragment<wmma::accumulator, 16, 16, 8, float> acc[4][2];
    #pragma unroll
    for (int i = 0; i < 4; i++)
        #pragma unroll
        for (int j = 0; j < 2; j++) wmma::fill_fragment(acc[i][j], 0.0f);

    // global load mapping: thread covers rows {lr, lr+64}, cols lc..lc+7
    int lr = tid >> 2;            // 0..63
    int lc = (tid & 3) * 8;       // 0,8,16,24
    const float* Ag = A + (size_t)(bm * BM + lr) * K + lc;
    const float* Bg = B + (size_t)(bn * BN + lr) * K + lc;
    const size_t g64 = (size_t)64 * K;

    int KT = K / BK;

    // issue loads for k-tile kt into buffer buf
    auto issue = [&](int kt, int buf) {
        const float* a = Ag + kt * BK;
        const float* b = Bg + kt * BK;
        float* as = As + buf * BM * LDS_K;
        float* bs = Bs + buf * BN * LDS_K;
        cp_async16(as + lr * LDS_K + lc,            a);
        cp_async16(as + lr * LDS_K + lc + 4,        a + 4);
        cp_async16(as + (lr + 64) * LDS_K + lc,     a + g64);
        cp_async16(as + (lr + 64) * LDS_K + lc + 4, a + g64 + 4);
        cp_async16(bs + lr * LDS_K + lc,            b);
        cp_async16(bs + lr * LDS_K + lc + 4,        b + 4);
        cp_async16(bs + (lr + 64) * LDS_K + lc,     b + g64);
        cp_async16(bs + (lr + 64) * LDS_K + lc + 4, b + g64 + 4);
    };

    issue(0, 0);
    cp_commit();

    for (int kt = 0; kt < KT; kt++) {
        if (kt + 1 < KT) {
            issue(kt + 1, (kt + 1) & 1);
            cp_commit();
            cp_wait<1>();
        } else {
            cp_wait<0>();
        }
        __syncthreads();

        const float* as = As + (kt & 1) * BM * LDS_K + (wm * 64) * LDS_K;
        const float* bs = Bs + (kt & 1) * BN * LDS_K + (wn * 32) * LDS_K;

        #pragma unroll
        for (int kk = 0; kk < BK; kk += 8) {
            wmma::fragment<wmma::matrix_a, 16, 16, 8, wmma::precision::tf32, wmma::row_major> af[4];
            wmma::fragment<wmma::matrix_b, 16, 16, 8, wmma::precision::tf32, wmma::col_major> bf[2];
            #pragma unroll
            for (int i = 0; i < 4; i++) {
                wmma::load_matrix_sync(af[i], as + (i * 16) * LDS_K + kk, LDS_K);
                #pragma unroll
                for (int t = 0; t < af[i].num_elements; t++)
                    af[i].x[t] = wmma::__float_to_tf32(af[i].x[t]);
            }
            #pragma unroll
            for (int j = 0; j < 2; j++) {
                wmma::load_matrix_sync(bf[j], bs + (j * 16) * LDS_K + kk, LDS_K);
                #pragma unroll
                for (int t = 0; t < bf[j].num_elements; t++)
                    bf[j].x[t] = wmma::__float_to_tf32(bf[j].x[t]);
            }
            #pragma unroll
            for (int i = 0; i < 4; i++)
                #pragma unroll
                for (int j = 0; j < 2; j++)
                    wmma::mma_sync(acc[i][j], af[i], bf[j], acc[i][j]);
        }
        __syncthreads();
    }

    // epilogue: stage C tile in smem (reuses the pipeline buffers)
    float* Cs = smem;   // [BM][LDC_S]
    #pragma unroll
    for (int i = 0; i < 4; i++)
        #pragma unroll
        for (int j = 0; j < 2; j++)
            wmma::store_matrix_sync(Cs + (wm * 64 + i * 16) * LDC_S + wn * 32 + j * 16,
                                    acc[i][j], LDC_S, wmma::mem_row_major);
    __syncthreads();

    int m0 = bm * BM, n0 = bn * BN;
    #pragma unroll
    for (int it = 0; it < 16; it++) {
        int idx = tid + it * 256;          // 0..4095 float4 slots
        int r  = idx >> 5;                 // 0..127
        int c4 = (idx & 31) * 4;           // 0..124
        float4 v = *(const float4*)&Cs[r * LDC_S + c4];
        float4 bv = *(const float4*)(bias + n0 + c4);
        v.x += bv.x; v.y += bv.y; v.z += bv.z; v.w += bv.w;
        if (EPI == 1) {
            v.x = gelu_exact(v.x); v.y = gelu_exact(v.y);
            v.z = gelu_exact(v.z); v.w = gelu_exact(v.w);
        }
        size_t off = (size_t)(m0 + r) * N + n0 + c4;
        if (EPI == 2) {
            float4 rv = *(const float4*)(res + off);
            v.x += rv.x; v.y += rv.y; v.z += rv.z; v.w += rv.w;
        }
        *(float4*)(C + off) = v;
    }
}

// ---------------- Causal flash attention, fp32 -----------------------------
#define AT_PAD 68
#define ATT_SMEM (4 * 64 * AT_PAD * 4)

__global__ void __launch_bounds__(256, 3)
attn_kernel(const float* __restrict__ qkv, float* __restrict__ y) {
    extern __shared__ __align__(16) float sm[];
    float* Qs = sm;
    float* Ks = Qs + 64 * AT_PAD;
    float* Vs = Ks + 64 * AT_PAD;
    float* Ps = Vs + 64 * AT_PAD;

    int qb = blockIdx.x, h = blockIdx.y, b = blockIdx.z;
    int tid = threadIdx.x;
    int ty = tid >> 4, tx = tid & 15;
    size_t base = (size_t)b * TSEQ * D3;
    int hoff = h * DHEAD;

    #pragma unroll
    for (int i = 0; i < 4; i++) {
        int v = tid + i * 256;
        int rr = v >> 4;
        int cc = (v & 15) * 4;
        *(float4*)&Qs[rr * AT_PAD + cc] =
            *(const float4*)(qkv + base + (size_t)(qb * 64 + rr) * D3 + hoff + cc);
    }

    float m_i[4], l_i[4], o[4][4];
    #pragma unroll
    for (int i = 0; i < 4; i++) {
        m_i[i] = -INFINITY; l_i[i] = 0.f;
        #pragma unroll
        for (int j = 0; j < 4; j++) o[i][j] = 0.f;
    }

    for (int kb = 0; kb <= qb; kb++) {
        __syncthreads();
        #pragma unroll
        for (int i = 0; i < 4; i++) {
            int v = tid + i * 256;
            int rr = v >> 4;
            int cc = (v & 15) * 4;
            size_t rowb = base + (size_t)(kb * 64 + rr) * D3 + hoff;
            *(float4*)&Ks[rr * AT_PAD + cc] = *(const float4*)(qkv + rowb + 1024 + cc);
            *(float4*)&Vs[rr * AT_PAD + cc] = *(const float4*)(qkv + rowb + 2048 + cc);
        }
        __syncthreads();

        float s[4][4];
        #pragma unroll
        for (int i = 0; i < 4; i++)
            #pragma unroll
            for (int j = 0; j < 4; j++) s[i][j] = 0.f;

        for (int d = 0; d < DHEAD; d += 4) {
            float4 qv[4], kv[4];
            #pragma unroll
            for (int i = 0; i < 4; i++) qv[i] = *(const float4*)&Qs[(ty * 4 + i) * AT_PAD + d];
            #pragma unroll
            for (int j = 0; j < 4; j++) kv[j] = *(const float4*)&Ks[(tx * 4 + j) * AT_PAD + d];
            #pragma unroll
            for (int i = 0; i < 4; i++)
                #pragma unroll
                for (int j = 0; j < 4; j++)
                    s[i][j] += qv[i].x * kv[j].x + qv[i].y * kv[j].y +
                               qv[i].z * kv[j].z + qv[i].w * kv[j].w;
        }

        const float sc = 0.125f;
        #pragma unroll
        for (int i = 0; i < 4; i++)
            #pragma unroll
            for (int j = 0; j < 4; j++) s[i][j] *= sc;
        if (kb == qb) {
            #pragma unroll
            for (int i = 0; i < 4; i++)
                #pragma unroll
                for (int j = 0; j < 4; j++)
                    if (tx * 4 + j > ty * 4 + i) s[i][j] = -1e30f;
        }

        #pragma unroll
        for (int i = 0; i < 4; i++) {
            float mx = fmaxf(fmaxf(s[i][0], s[i][1]), fmaxf(s[i][2], s[i][3]));
            #pragma unroll
            for (int off = 8; off >= 1; off >>= 1)
                mx = fmaxf(mx, __shfl_xor_sync(0xffffffffu, mx, off, 16));
            float mnew = fmaxf(m_i[i], mx);
            float f = __expf(m_i[i] - mnew);
            m_i[i] = mnew;
            float rsum = 0.f;
            #pragma unroll
            for (int j = 0; j < 4; j++) { s[i][j] = __expf(s[i][j] - mnew); rsum += s[i][j]; }
            #pragma unroll
            for (int off = 8; off >= 1; off >>= 1)
                rsum += __shfl_xor_sync(0xffffffffu, rsum, off, 16);
            l_i[i] = l_i[i] * f + rsum;
            #pragma unroll
            for (int j = 0; j < 4; j++) o[i][j] *= f;
            *(float4*)&Ps[(ty * 4 + i) * AT_PAD + tx * 4] =
                make_float4(s[i][0], s[i][1], s[i][2], s[i][3]);
        }
        __syncthreads();

        for (int k = 0; k < 64; k += 4) {
            float4 pv[4], vv[4];
            #pragma unroll
            for (int i = 0; i < 4; i++) pv[i] = *(const float4*)&Ps[(ty * 4 + i) * AT_PAD + k];
            #pragma unroll
            for (int kk = 0; kk < 4; kk++) vv[kk] = *(const float4*)&Vs[(k + kk) * AT_PAD + tx * 4];
            #pragma unroll
            for (int i = 0; i < 4; i++) {
                float* vr0 = (float*)&vv[0];
                float* vr1 = (float*)&vv[1];
                float* vr2 = (float*)&vv[2];
                float* vr3 = (float*)&vv[3];
                #pragma unroll
                for (int j = 0; j < 4; j++)
                    o[i][j] += pv[i].x * vr0[j] + pv[i].y * vr1[j] +
                               pv[i].z * vr2[j] + pv[i].w * vr3[j];
            }
        }
    }

    #pragma unroll
    for (int i = 0; i < 4; i++) {
        float inv = 1.0f / l_i[i];
        int q = qb * 64 + ty * 4 + i;
        *(float4*)(y + (size_t)(b * TSEQ + q) * DMODEL + hoff + tx * 4) =
            make_float4(o[i][0] * inv, o[i][1] * inv, o[i][2] * inv, o[i][3] * inv);
    }
}

// ---------------- launch ---------------------------------------------------
static float* symaddr(const void* sym) {
    void* p = nullptr;
    cudaGetSymbolAddress(&p, sym);
    return (float*)p;
}

extern "C" void kernel_launch(void* const* d_in, const int* in_sizes, int n_in,
                              void* d_out, int out_size) {
    const float* x      = (const float*)d_in[0];
    const float* ln1_w  = (const float*)d_in[1];
    const float* ln1_b  = (const float*)d_in[2];
    const float* qkv_w  = (const float*)d_in[3];
    const float* qkv_b  = (const float*)d_in[4];
    const float* out_w  = (const float*)d_in[5];
    const float* out_b  = (const float*)d_in[6];
    const float* ln2_w  = (const float*)d_in[7];
    const float* ln2_b  = (const float*)d_in[8];
    const float* mlp_w1 = (const float*)d_in[9];
    const float* mlp_b1 = (const float*)d_in[10];
    const float* mlp_w2 = (const float*)d_in[11];
    const float* mlp_b2 = (const float*)d_in[12];
    float* out = (float*)d_out;

    float* xln = symaddr(g_xln);
    float* qkv = symaddr(g_qkv);
    float* y   = symaddr(g_y);
    float* x1  = symaddr(g_x1);
    float* h   = symaddr(g_h);
    float* act = symaddr(g_act);

    cudaFuncSetAttribute(attn_kernel, cudaFuncAttributeMaxDynamicSharedMemorySize, ATT_SMEM);
    cudaFuncSetAttribute(gemm_tf32<0>, cudaFuncAttributeMaxDynamicSharedMemorySize, GEMM_SMEM);
    cudaFuncSetAttribute(gemm_tf32<1>, cudaFuncAttributeMaxDynamicSharedMemorySize, GEMM_SMEM);
    cudaFuncSetAttribute(gemm_tf32<2>, cudaFuncAttributeMaxDynamicSharedMemorySize, GEMM_SMEM);

    // 1. LN1
    ln_kernel<<<MROWS, 256>>>(x, ln1_w, ln1_b, xln);
    // 2. QKV projection: [4096,1024] x [3072,1024]^T
    gemm_tf32<0><<<dim3(D3 / BN, MROWS / BM), 256, GEMM_SMEM>>>(xln, qkv_w, qkv_b, nullptr, qkv, D3, DMODEL);
    // 3. causal attention
    attn_kernel<<<dim3(TSEQ / 64, NHEAD, 2), 256, ATT_SMEM>>>(qkv, y);
    // 4. out projection + residual -> x1
    gemm_tf32<2><<<dim3(DMODEL / BN, MROWS / BM), 256, GEMM_SMEM>>>(y, out_w, out_b, x, x1, DMODEL, DMODEL);
    // 5. LN2
    ln_kernel<<<MROWS, 256>>>(x1, ln2_w, ln2_b, h);
    // 6. MLP up + exact GELU
    gemm_tf32<1><<<dim3(DFF / BN, MROWS / BM), 256, GEMM_SMEM>>>(h, mlp_w1, mlp_b1, nullptr, act, DFF, DMODEL);
    // 7. MLP down + residual -> output
    gemm_tf32<2><<<dim3(DMODEL / BN, MROWS / BM), 256, GEMM_SMEM>>>(act, mlp_w2, mlp_b2, x1, out, DMODEL, DFF);
}

// round 5
// speedup vs baseline: 2.4807x; 1.9912x over previous
#include <cuda_runtime.h>
#include <cuda_fp16.h>
#include <mma.h>
#include <math.h>
#include <stdint.h>

using namespace nvcuda;

// Problem constants
#define MROWS  4096      // B*T
#define DMODEL 1024
#define D3     3072
#define DFF    4096
#define TSEQ   2048
#define NHEAD  16
#define DHEAD  64

// ---------------- scratch (device globals: no runtime allocation) ----------
__device__ float g_qkv[(size_t)MROWS * D3];
__device__ float g_x1 [(size_t)MROWS * DMODEL];
__device__ __align__(16) __half g_xln_h[(size_t)MROWS * DMODEL];
__device__ __align__(16) __half g_y_h  [(size_t)MROWS * DMODEL];
__device__ __align__(16) __half g_h_h  [(size_t)MROWS * DMODEL];
__device__ __align__(16) __half g_act_h[(size_t)MROWS * DFF];
__device__ __align__(16) __half g_wq_h [(size_t)D3 * DMODEL];
__device__ __align__(16) __half g_wo_h [(size_t)DMODEL * DMODEL];
__device__ __align__(16) __half g_w1_h [(size_t)DFF * DMODEL];
__device__ __align__(16) __half g_w2_h [(size_t)DMODEL * DFF];

// ---------------- helpers ---------------------------------------------------
__device__ __forceinline__ uint32_t smem_u32(const void* p) {
    uint32_t a;
    asm("{ .reg .u64 t; cvta.to.shared.u64 t, %1; cvt.u32.u64 %0, t; }" : "=r"(a) : "l"(p));
    return a;
}
__device__ __forceinline__ void cpa16(uint32_t s, const void* g) {
    asm volatile("cp.async.cg.shared.global [%0], [%1], 16;" :: "r"(s), "l"(g));
}
__device__ __forceinline__ void cp_commit() { asm volatile("cp.async.commit_group;"); }
template <int N>
__device__ __forceinline__ void cp_wait() { asm volatile("cp.async.wait_group %0;" :: "n"(N)); }

__device__ __forceinline__ float gelu_exact(float v) {
    return 0.5f * v * (1.0f + erff(v * 0.70710678118654752f));
}

// ---------------- float -> half convert -------------------------------------
__global__ void f2h_kernel(const float4* __restrict__ src, __half2* __restrict__ dst, int n4) {
    int i = blockIdx.x * blockDim.x + threadIdx.x;
    if (i < n4) {
        float4 v = src[i];
        dst[2 * i]     = __floats2half2_rn(v.x, v.y);
        dst[2 * i + 1] = __floats2half2_rn(v.z, v.w);
    }
}

// ---------------- LayerNorm (fp32 in, half out) -----------------------------
__global__ void ln_kernel(const float* __restrict__ x,
                          const float* __restrict__ w,
                          const float* __restrict__ b,
                          __half* __restrict__ out) {
    int row = blockIdx.x;
    int tid = threadIdx.x;                       // 256 threads, 4 floats each
    const float* xr = x + (size_t)row * DMODEL;

    float4 v = *(const float4*)(xr + tid * 4);
    float s  = v.x + v.y + v.z + v.w;
    float ss = v.x * v.x + v.y * v.y + v.z * v.z + v.w * v.w;

    #pragma unroll
    for (int off = 16; off >= 1; off >>= 1) {
        s  += __shfl_xor_sync(0xffffffffu, s,  off);
        ss += __shfl_xor_sync(0xffffffffu, ss, off);
    }
    __shared__ float rs[8], rss[8];
    __shared__ float stats[2];
    int wid = tid >> 5, lane = tid & 31;
    if (lane == 0) { rs[wid] = s; rss[wid] = ss; }
    __syncthreads();
    if (tid == 0) {
        float S = 0.f, SS = 0.f;
        #pragma unroll
        for (int i = 0; i < 8; i++) { S += rs[i]; SS += rss[i]; }
        float mu  = S * (1.0f / DMODEL);
        float var = SS * (1.0f / DMODEL) - mu * mu;
        stats[0] = mu;
        stats[1] = rsqrtf(var + 1e-5f);
    }
    __syncthreads();
    float mu = stats[0], r = stats[1];

    float4 wv = *(const float4*)(w + tid * 4);
    float4 bv = *(const float4*)(b + tid * 4);
    float o0 = (v.x - mu) * r * wv.x + bv.x;
    float o1 = (v.y - mu) * r * wv.y + bv.y;
    float o2 = (v.z - mu) * r * wv.z + bv.z;
    float o3 = (v.w - mu) * r * wv.w + bv.w;
    __half2* orow = (__half2*)(out + (size_t)row * DMODEL);
    orow[tid * 2]     = __floats2half2_rn(o0, o1);
    orow[tid * 2 + 1] = __floats2half2_rn(o2, o3);
}

// ---------------- fp16 tensor-core GEMM NT ----------------------------------
// C[M,N] = A[M,K] * B[N,K]^T + bias (+epilogue).
// EPI: 0=none, 1=GELU, 2=residual.  HOUT: 1 -> write half to Ch instead of C.
#define GSTG 4
#define LDH 40                              // halves per smem row (32 + 8 pad)
#define STAGE_H (256 * LDH)                 // halves per stage (A 128 + B 128 rows)
#define STAGE_B (STAGE_H * 2)               // 20480 bytes
#define GEMM_SMEM_H (GSTG * STAGE_B)        // 81920 bytes

template <int EPI, int HOUT>
__global__ void __launch_bounds__(256, 2)
gemm_h(const __half* __restrict__ A, const __half* __restrict__ B,
       const float* __restrict__ bias, const float* __restrict__ res,
       float* __restrict__ C, __half* __restrict__ Ch, int N, int K) {
    extern __shared__ __align__(16) __half sm[];
    uint32_t sb = smem_u32(sm);

    int tid = threadIdx.x;
    int wid = tid >> 5;
    int bn = blockIdx.x, bm = blockIdx.y;
    int wm = wid >> 2;            // 0..1 : 64-row slab
    int wn = wid & 3;             // 0..3 : 32-col slab
    const int KT = K >> 5;        // K / 32

    wmma::fragment<wmma::accumulator, 16, 16, 16, float> acc[4][2];
    #pragma unroll
    for (int i = 0; i < 4; i++)
        #pragma unroll
        for (int j = 0; j < 2; j++) wmma::fill_fragment(acc[i][j], 0.0f);

    const __half* Ab = A + (size_t)(bm * 128) * K;
    const __half* Bb = B + (size_t)(bn * 128) * K;

    // 1024 x 16B chunks per stage: c<512 -> A rows, else B rows.
    // row = (c>>2)&127, q = c&3 (16B sub-chunk). A part bytes [0,10240), B at +10240.
    auto issue = [&](int kt) {
        uint32_t dst = sb + (uint32_t)(kt & (GSTG - 1)) * STAGE_B;
        #pragma unroll
        for (int i = 0; i < 4; i++) {
            int c = i * 256 + tid;
            int isB = c >> 9;
            int row = (c >> 2) & 127;
            int q = c & 3;
            const __half* g = (isB ? Bb : Ab) + (size_t)row * K + kt * 32 + q * 8;
            cpa16(dst + (isB ? STAGE_H : 0) + (uint32_t)(row * LDH + q * 8) * 2, g);
        }
    };

    // prologue: 3 stages in flight
    #pragma unroll
    for (int p = 0; p < GSTG - 1; p++) { issue(p); cp_commit(); }

    for (int kt = 0; kt < KT; kt++) {
        bool more = (kt + GSTG - 1 < KT);
        if (more) cp_wait<GSTG - 2>();   // stage kt landed (2 newer groups pending)
        else      cp_wait<0>();          // tail: no further commits -> drain all
        __syncthreads();                 // all threads done reading stage (kt-1)%4
        if (more) { issue(kt + GSTG - 1); cp_commit(); }

        const __half* sA = sm + (size_t)(kt & (GSTG - 1)) * STAGE_H + (size_t)(wm * 64) * LDH;
        const __half* sB = sm + (size_t)(kt & (GSTG - 1)) * STAGE_H + (size_t)(STAGE_H / 2) + (size_t)(wn * 32) * LDH;

        #pragma unroll
        for (int ks = 0; ks < 32; ks += 16) {
            wmma::fragment<wmma::matrix_a, 16, 16, 16, __half, wmma::row_major> af;
            wmma::fragment<wmma::matrix_b, 16, 16, 16, __half, wmma::col_major> bf[2];
            #pragma unroll
            for (int j = 0; j < 2; j++)
                wmma::load_matrix_sync(bf[j], sB + (j * 16) * LDH + ks, LDH);
            #pragma unroll
            for (int i = 0; i < 4; i++) {
                wmma::load_matrix_sync(af, sA + (i * 16) * LDH + ks, LDH);
                #pragma unroll
                for (int j = 0; j < 2; j++)
                    wmma::mma_sync(acc[i][j], af, bf[j], acc[i][j]);
            }
        }
    }

    // ---- epilogue: stage through smem ----
    __syncthreads();
    float* Cs = (float*)sm;           // [128][132] = 67584 B, fits in 81920
    #pragma unroll
    for (int i = 0; i < 4; i++)
        #pragma unroll
        for (int j = 0; j < 2; j++)
            wmma::store_matrix_sync(Cs + (wm * 64 + i * 16) * 132 + wn * 32 + j * 16,
                                    acc[i][j], 132, wmma::mem_row_major);
    __syncthreads();

    int m0 = bm * 128, n0 = bn * 128;
    #pragma unroll
    for (int it = 0; it < 16; it++) {
        int idx = tid + it * 256;          // 0..4095
        int r  = idx >> 5;                 // 0..127
        int c4 = (idx & 31) * 4;           // 0..124
        float4 v = *(const float4*)&Cs[r * 132 + c4];
        float4 bv = *(const float4*)(bias + n0 + c4);
        v.x += bv.x; v.y += bv.y; v.z += bv.z; v.w += bv.w;
        if (EPI == 1) {
            v.x = gelu_exact(v.x); v.y = gelu_exact(v.y);
            v.z = gelu_exact(v.z); v.w = gelu_exact(v.w);
        }
        size_t off = (size_t)(m0 + r) * N + n0 + c4;
        if (EPI == 2) {
            float4 rv = *(const float4*)(res + off);
            v.x += rv.x; v.y += rv.y; v.z += rv.z; v.w += rv.w;
        }
        if (HOUT) {
            __half2* hp = (__half2*)(Ch + off);
            hp[0] = __floats2half2_rn(v.x, v.y);
            hp[1] = __floats2half2_rn(v.z, v.w);
        } else {
            *(float4*)(C + off) = v;
        }
    }
}

// ---------------- Causal flash attention, fp32 (half output) ----------------
#define AT_PAD 68
#define ATT_SMEM (4 * 64 * AT_PAD * 4)

__global__ void __launch_bounds__(256, 3)
attn_kernel(const float* __restrict__ qkv, __half* __restrict__ y) {
    extern __shared__ __align__(16) float smf[];
    float* Qs = smf;
    float* Ks = Qs + 64 * AT_PAD;
    float* Vs = Ks + 64 * AT_PAD;
    float* Ps = Vs + 64 * AT_PAD;

    int qb = blockIdx.x, h = blockIdx.y, b = blockIdx.z;
    int tid = threadIdx.x;
    int ty = tid >> 4, tx = tid & 15;
    size_t base = (size_t)b * TSEQ * D3;
    int hoff = h * DHEAD;

    #pragma unroll
    for (int i = 0; i < 4; i++) {
        int v = tid + i * 256;
        int rr = v >> 4;
        int cc = (v & 15) * 4;
        *(float4*)&Qs[rr * AT_PAD + cc] =
            *(const float4*)(qkv + base + (size_t)(qb * 64 + rr) * D3 + hoff + cc);
    }

    float m_i[4], l_i[4], o[4][4];
    #pragma unroll
    for (int i = 0; i < 4; i++) {
        m_i[i] = -INFINITY; l_i[i] = 0.f;
        #pragma unroll
        for (int j = 0; j < 4; j++) o[i][j] = 0.f;
    }

    for (int kb = 0; kb <= qb; kb++) {
        __syncthreads();
        #pragma unroll
        for (int i = 0; i < 4; i++) {
            int v = tid + i * 256;
            int rr = v >> 4;
            int cc = (v & 15) * 4;
            size_t rowb = base + (size_t)(kb * 64 + rr) * D3 + hoff;
            *(float4*)&Ks[rr * AT_PAD + cc] = *(const float4*)(qkv + rowb + 1024 + cc);
            *(float4*)&Vs[rr * AT_PAD + cc] = *(const float4*)(qkv + rowb + 2048 + cc);
        }
        __syncthreads();

        float s[4][4];
        #pragma unroll
        for (int i = 0; i < 4; i++)
            #pragma unroll
            for (int j = 0; j < 4; j++) s[i][j] = 0.f;

        for (int d = 0; d < DHEAD; d += 4) {
            float4 qv[4], kv[4];
            #pragma unroll
            for (int i = 0; i < 4; i++) qv[i] = *(const float4*)&Qs[(ty * 4 + i) * AT_PAD + d];
            #pragma unroll
            for (int j = 0; j < 4; j++) kv[j] = *(const float4*)&Ks[(tx * 4 + j) * AT_PAD + d];
            #pragma unroll
            for (int i = 0; i < 4; i++)
                #pragma unroll
                for (int j = 0; j < 4; j++)
                    s[i][j] += qv[i].x * kv[j].x + qv[i].y * kv[j].y +
                               qv[i].z * kv[j].z + qv[i].w * kv[j].w;
        }

        const float sc = 0.125f;
        #pragma unroll
        for (int i = 0; i < 4; i++)
            #pragma unroll
            for (int j = 0; j < 4; j++) s[i][j] *= sc;
        if (kb == qb) {
            #pragma unroll
            for (int i = 0; i < 4; i++)
                #pragma unroll
                for (int j = 0; j < 4; j++)
                    if (tx * 4 + j > ty * 4 + i) s[i][j] = -1e30f;
        }

        #pragma unroll
        for (int i = 0; i < 4; i++) {
            float mx = fmaxf(fmaxf(s[i][0], s[i][1]), fmaxf(s[i][2], s[i][3]));
            #pragma unroll
            for (int off = 8; off >= 1; off >>= 1)
                mx = fmaxf(mx, __shfl_xor_sync(0xffffffffu, mx, off, 16));
            float mnew = fmaxf(m_i[i], mx);
            float f = __expf(m_i[i] - mnew);
            m_i[i] = mnew;
            float rsum = 0.f;
            #pragma unroll
            for (int j = 0; j < 4; j++) { s[i][j] = __expf(s[i][j] - mnew); rsum += s[i][j]; }
            #pragma unroll
            for (int off = 8; off >= 1; off >>= 1)
                rsum += __shfl_xor_sync(0xffffffffu, rsum, off, 16);
            l_i[i] = l_i[i] * f + rsum;
            #pragma unroll
            for (int j = 0; j < 4; j++) o[i][j] *= f;
            *(float4*)&Ps[(ty * 4 + i) * AT_PAD + tx * 4] =
                make_float4(s[i][0], s[i][1], s[i][2], s[i][3]);
        }
        __syncthreads();

        for (int k = 0; k < 64; k += 4) {
            float4 pv[4], vv[4];
            #pragma unroll
            for (int i = 0; i < 4; i++) pv[i] = *(const float4*)&Ps[(ty * 4 + i) * AT_PAD + k];
            #pragma unroll
            for (int kk = 0; kk < 4; kk++) vv[kk] = *(const float4*)&Vs[(k + kk) * AT_PAD + tx * 4];
            #pragma unroll
            for (int i = 0; i < 4; i++) {
                float* vr0 = (float*)&vv[0];
                float* vr1 = (float*)&vv[1];
                float* vr2 = (float*)&vv[2];
                float* vr3 = (float*)&vv[3];
                #pragma unroll
                for (int j = 0; j < 4; j++)
                    o[i][j] += pv[i].x * vr0[j] + pv[i].y * vr1[j] +
                               pv[i].z * vr2[j] + pv[i].w * vr3[j];
            }
        }
    }

    #pragma unroll
    for (int i = 0; i < 4; i++) {
        float inv = 1.0f / l_i[i];
        int q = qb * 64 + ty * 4 + i;
        __half2* yp = (__half2*)(y + (size_t)(b * TSEQ + q) * DMODEL + hoff + tx * 4);
        yp[0] = __floats2half2_rn(o[i][0] * inv, o[i][1] * inv);
        yp[1] = __floats2half2_rn(o[i][2] * inv, o[i][3] * inv);
    }
}

// ---------------- launch ----------------------------------------------------
template <typename T>
static T* symaddr(const void* sym) {
    void* p = nullptr;
    cudaGetSymbolAddress(&p, sym);
    return (T*)p;
}

extern "C" void kernel_launch(void* const* d_in, const int* in_sizes, int n_in,
                              void* d_out, int out_size) {
    const float* x      = (const float*)d_in[0];
    const float* ln1_w  = (const float*)d_in[1];
    const float* ln1_b  = (const float*)d_in[2];
    const float* qkv_w  = (const float*)d_in[3];
    const float* qkv_b  = (const float*)d_in[4];
    const float* out_w  = (const float*)d_in[5];
    const float* out_b  = (const float*)d_in[6];
    const float* ln2_w  = (const float*)d_in[7];
    const float* ln2_b  = (const float*)d_in[8];
    const float* mlp_w1 = (const float*)d_in[9];
    const float* mlp_b1 = (const float*)d_in[10];
    const float* mlp_w2 = (const float*)d_in[11];
    const float* mlp_b2 = (const float*)d_in[12];
    float* out = (float*)d_out;

    float*  qkv  = symaddr<float>(g_qkv);
    float*  x1   = symaddr<float>(g_x1);
    __half* xlnh = symaddr<__half>(g_xln_h);
    __half* yh   = symaddr<__half>(g_y_h);
    __half* hh   = symaddr<__half>(g_h_h);
    __half* acth = symaddr<__half>(g_act_h);
    __half* wqh  = symaddr<__half>(g_wq_h);
    __half* woh  = symaddr<__half>(g_wo_h);
    __half* w1h  = symaddr<__half>(g_w1_h);
    __half* w2h  = symaddr<__half>(g_w2_h);

    cudaFuncSetAttribute(attn_kernel, cudaFuncAttributeMaxDynamicSharedMemorySize, ATT_SMEM);
    cudaFuncSetAttribute(gemm_h<0,0>, cudaFuncAttributeMaxDynamicSharedMemorySize, GEMM_SMEM_H);
    cudaFuncSetAttribute(gemm_h<1,1>, cudaFuncAttributeMaxDynamicSharedMemorySize, GEMM_SMEM_H);
    cudaFuncSetAttribute(gemm_h<2,0>, cudaFuncAttributeMaxDynamicSharedMemorySize, GEMM_SMEM_H);

    // 0. weights -> half (every launch; deterministic, ~15us)
    f2h_kernel<<<(D3 * DMODEL / 4 + 255) / 256, 256>>>((const float4*)qkv_w, (__half2*)wqh, D3 * DMODEL / 4);
    f2h_kernel<<<(DMODEL * DMODEL / 4 + 255) / 256, 256>>>((const float4*)out_w, (__half2*)woh, DMODEL * DMODEL / 4);
    f2h_kernel<<<(DFF * DMODEL / 4 + 255) / 256, 256>>>((const float4*)mlp_w1, (__half2*)w1h, DFF * DMODEL / 4);
    f2h_kernel<<<(DMODEL * DFF / 4 + 255) / 256, 256>>>((const float4*)mlp_w2, (__half2*)w2h, DMODEL * DFF / 4);

    // 1. LN1 -> half
    ln_kernel<<<MROWS, 256>>>(x, ln1_w, ln1_b, xlnh);
    // 2. QKV projection -> fp32 qkv
    gemm_h<0,0><<<dim3(D3 / 128, MROWS / 128), 256, GEMM_SMEM_H>>>(xlnh, wqh, qkv_b, nullptr, qkv, nullptr, D3, DMODEL);
    // 3. causal attention -> half y
    attn_kernel<<<dim3(TSEQ / 64, NHEAD, 2), 256, ATT_SMEM>>>(qkv, yh);
    // 4. out projection + residual -> fp32 x1
    gemm_h<2,0><<<dim3(DMODEL / 128, MROWS / 128), 256, GEMM_SMEM_H>>>(yh, woh, out_b, x, x1, nullptr, DMODEL, DMODEL);
    // 5. LN2 -> half
    ln_kernel<<<MROWS, 256>>>(x1, ln2_w, ln2_b, hh);
    // 6. MLP up + exact GELU -> half act
    gemm_h<1,1><<<dim3(DFF / 128, MROWS / 128), 256, GEMM_SMEM_H>>>(hh, w1h, mlp_b1, nullptr, nullptr, acth, DFF, DMODEL);
    // 7. MLP down + residual -> fp32 output
    gemm_h<2,0><<<dim3(DMODEL / 128, MROWS / 128), 256, GEMM_SMEM_H>>>(acth, w2h, mlp_b2, x1, out, nullptr, DMODEL, DFF);
}

// round 7
// speedup vs baseline: 6.1383x; 2.4744x over previous
#include <cuda_runtime.h>
#include <cuda_fp16.h>
#include <mma.h>
#include <math.h>
#include <stdint.h>

using namespace nvcuda;

// Problem constants
#define MROWS  4096      // B*T
#define DMODEL 1024
#define D3     3072
#define DFF    4096
#define TSEQ   2048
#define NHEAD  16
#define DHEAD  64

// ---------------- scratch (device globals: no runtime allocation) ----------
__device__ float g_x1 [(size_t)MROWS * DMODEL];
__device__ __align__(16) __half g_qkv_h[(size_t)MROWS * D3];
__device__ __align__(16) __half g_xln_h[(size_t)MROWS * DMODEL];
__device__ __align__(16) __half g_y_h  [(size_t)MROWS * DMODEL];
__device__ __align__(16) __half g_h_h  [(size_t)MROWS * DMODEL];
__device__ __align__(16) __half g_act_h[(size_t)MROWS * DFF];
__device__ __align__(16) __half g_wq_h [(size_t)D3 * DMODEL];
__device__ __align__(16) __half g_wo_h [(size_t)DMODEL * DMODEL];
__device__ __align__(16) __half g_w1_h [(size_t)DFF * DMODEL];
__device__ __align__(16) __half g_w2_h [(size_t)DMODEL * DFF];

// ---------------- helpers ---------------------------------------------------
__device__ __forceinline__ uint32_t smem_u32(const void* p) {
    uint32_t a;
    asm("{ .reg .u64 t; cvta.to.shared.u64 t, %1; cvt.u32.u64 %0, t; }" : "=r"(a) : "l"(p));
    return a;
}
__device__ __forceinline__ void cpa16(uint32_t s, const void* g) {
    asm volatile("cp.async.cg.shared.global [%0], [%1], 16;" :: "r"(s), "l"(g));
}
__device__ __forceinline__ void cp_commit() { asm volatile("cp.async.commit_group;"); }
template <int N>
__device__ __forceinline__ void cp_wait() { asm volatile("cp.async.wait_group %0;" :: "n"(N)); }

__device__ __forceinline__ float gelu_exact(float v) {
    return 0.5f * v * (1.0f + erff(v * 0.70710678118654752f));
}

// mma.m16n8k16 fp16 -> fp32, row.col
__device__ __forceinline__ void mma16816(float* c, const uint32_t* a, const uint32_t* b) {
    asm volatile(
        "mma.sync.aligned.m16n8k16.row.col.f32.f16.f16.f32 "
        "{%0,%1,%2,%3}, {%4,%5,%6,%7}, {%8,%9}, {%0,%1,%2,%3};"
        : "+f"(c[0]), "+f"(c[1]), "+f"(c[2]), "+f"(c[3])
        : "r"(a[0]), "r"(a[1]), "r"(a[2]), "r"(a[3]), "r"(b[0]), "r"(b[1]));
}
__device__ __forceinline__ uint32_t pack_h2(float x, float y) {
    __half2 h = __floats2half2_rn(x, y);
    return *(uint32_t*)&h;
}

// ---------------- float -> half convert -------------------------------------
__global__ void f2h_kernel(const float4* __restrict__ src, __half2* __restrict__ dst, int n4) {
    int i = blockIdx.x * blockDim.x + threadIdx.x;
    if (i < n4) {
        float4 v = src[i];
        dst[2 * i]     = __floats2half2_rn(v.x, v.y);
        dst[2 * i + 1] = __floats2half2_rn(v.z, v.w);
    }
}

// ---------------- LayerNorm (fp32 in, half out) -----------------------------
__global__ void ln_kernel(const float* __restrict__ x,
                          const float* __restrict__ w,
                          const float* __restrict__ b,
                          __half* __restrict__ out) {
    int row = blockIdx.x;
    int tid = threadIdx.x;
    const float* xr = x + (size_t)row * DMODEL;

    float4 v = *(const float4*)(xr + tid * 4);
    float s  = v.x + v.y + v.z + v.w;
    float ss = v.x * v.x + v.y * v.y + v.z * v.z + v.w * v.w;

    #pragma unroll
    for (int off = 16; off >= 1; off >>= 1) {
        s  += __shfl_xor_sync(0xffffffffu, s,  off);
        ss += __shfl_xor_sync(0xffffffffu, ss, off);
    }
    __shared__ float rs[8], rss[8];
    __shared__ float stats[2];
    int wid = tid >> 5, lane = tid & 31;
    if (lane == 0) { rs[wid] = s; rss[wid] = ss; }
    __syncthreads();
    if (tid == 0) {
        float S = 0.f, SS = 0.f;
        #pragma unroll
        for (int i = 0; i < 8; i++) { S += rs[i]; SS += rss[i]; }
        float mu  = S * (1.0f / DMODEL);
        float var = SS * (1.0f / DMODEL) - mu * mu;
        stats[0] = mu;
        stats[1] = rsqrtf(var + 1e-5f);
    }
    __syncthreads();
    float mu = stats[0], r = stats[1];

    float4 wv = *(const float4*)(w + tid * 4);
    float4 bv = *(const float4*)(b + tid * 4);
    float o0 = (v.x - mu) * r * wv.x + bv.x;
    float o1 = (v.y - mu) * r * wv.y + bv.y;
    float o2 = (v.z - mu) * r * wv.z + bv.z;
    float o3 = (v.w - mu) * r * wv.w + bv.w;
    __half2* orow = (__half2*)(out + (size_t)row * DMODEL);
    orow[tid * 2]     = __floats2half2_rn(o0, o1);
    orow[tid * 2 + 1] = __floats2half2_rn(o2, o3);
}

// ---------------- fp16 tensor-core GEMM NT ----------------------------------
#define GSTG 4
#define LDH 40
#define STAGE_H (256 * LDH)
#define STAGE_B (STAGE_H * 2)
#define GEMM_SMEM_H (GSTG * STAGE_B)        // 81920 bytes

template <int EPI, int HOUT>
__global__ void __launch_bounds__(256, 2)
gemm_h(const __half* __restrict__ A, const __half* __restrict__ B,
       const float* __restrict__ bias, const float* __restrict__ res,
       float* __restrict__ C, __half* __restrict__ Ch, int N, int K) {
    extern __shared__ __align__(16) __half sm[];
    uint32_t sb = smem_u32(sm);

    int tid = threadIdx.x;
    int wid = tid >> 5;
    int bn = blockIdx.x, bm = blockIdx.y;
    int wm = wid >> 2;
    int wn = wid & 3;
    const int KT = K >> 5;

    wmma::fragment<wmma::accumulator, 16, 16, 16, float> acc[4][2];
    #pragma unroll
    for (int i = 0; i < 4; i++)
        #pragma unroll
        for (int j = 0; j < 2; j++) wmma::fill_fragment(acc[i][j], 0.0f);

    const __half* Ab = A + (size_t)(bm * 128) * K;
    const __half* Bb = B + (size_t)(bn * 128) * K;

    auto issue = [&](int kt) {
        uint32_t dst = sb + (uint32_t)(kt & (GSTG - 1)) * STAGE_B;
        #pragma unroll
        for (int i = 0; i < 4; i++) {
            int c = i * 256 + tid;
            int isB = c >> 9;
            int row = (c >> 2) & 127;
            int q = c & 3;
            const __half* g = (isB ? Bb : Ab) + (size_t)row * K + kt * 32 + q * 8;
            cpa16(dst + (isB ? STAGE_H : 0) + (uint32_t)(row * LDH + q * 8) * 2, g);
        }
    };

    #pragma unroll
    for (int p = 0; p < GSTG - 1; p++) { issue(p); cp_commit(); }

    for (int kt = 0; kt < KT; kt++) {
        bool more = (kt + GSTG - 1 < KT);
        if (more) cp_wait<GSTG - 2>();
        else      cp_wait<0>();
        __syncthreads();
        if (more) { issue(kt + GSTG - 1); cp_commit(); }

        const __half* sA = sm + (size_t)(kt & (GSTG - 1)) * STAGE_H + (size_t)(wm * 64) * LDH;
        const __half* sB = sm + (size_t)(kt & (GSTG - 1)) * STAGE_H + (size_t)(STAGE_H / 2) + (size_t)(wn * 32) * LDH;

        #pragma unroll
        for (int ks = 0; ks < 32; ks += 16) {
            wmma::fragment<wmma::matrix_a, 16, 16, 16, __half, wmma::row_major> af;
            wmma::fragment<wmma::matrix_b, 16, 16, 16, __half, wmma::col_major> bf[2];
            #pragma unroll
            for (int j = 0; j < 2; j++)
                wmma::load_matrix_sync(bf[j], sB + (j * 16) * LDH + ks, LDH);
            #pragma unroll
            for (int i = 0; i < 4; i++) {
                wmma::load_matrix_sync(af, sA + (i * 16) * LDH + ks, LDH);
                #pragma unroll
                for (int j = 0; j < 2; j++)
                    wmma::mma_sync(acc[i][j], af, bf[j], acc[i][j]);
            }
        }
    }

    __syncthreads();
    float* Cs = (float*)sm;
    #pragma unroll
    for (int i = 0; i < 4; i++)
        #pragma unroll
        for (int j = 0; j < 2; j++)
            wmma::store_matrix_sync(Cs + (wm * 64 + i * 16) * 132 + wn * 32 + j * 16,
                                    acc[i][j], 132, wmma::mem_row_major);
    __syncthreads();

    int m0 = bm * 128, n0 = bn * 128;
    #pragma unroll
    for (int it = 0; it < 16; it++) {
        int idx = tid + it * 256;
        int r  = idx >> 5;
        int c4 = (idx & 31) * 4;
        float4 v = *(const float4*)&Cs[r * 132 + c4];
        float4 bv = *(const float4*)(bias + n0 + c4);
        v.x += bv.x; v.y += bv.y; v.z += bv.z; v.w += bv.w;
        if (EPI == 1) {
            v.x = gelu_exact(v.x); v.y = gelu_exact(v.y);
            v.z = gelu_exact(v.z); v.w = gelu_exact(v.w);
        }
        size_t off = (size_t)(m0 + r) * N + n0 + c4;
        if (EPI == 2) {
            float4 rv = *(const float4*)(res + off);
            v.x += rv.x; v.y += rv.y; v.z += rv.z; v.w += rv.w;
        }
        if (HOUT) {
            __half2* hp = (__half2*)(Ch + off);
            hp[0] = __floats2half2_rn(v.x, v.y);
            hp[1] = __floats2half2_rn(v.z, v.w);
        } else {
            *(float4*)(C + off) = v;
        }
    }
}

// ---------------- FA2-style fp16 attention ----------------------------------
// grid (T/64, H, B), 4 warps. Per warp: 16 query rows. mma.m16n8k16 PTX.
#define ATS 72    // smem stride (halves)

__global__ void __launch_bounds__(128)
attn_h(const __half* __restrict__ qkv, __half* __restrict__ y) {
    __shared__ __align__(16) __half Qs[64 * ATS];
    __shared__ __align__(16) __half Ks[64 * ATS];
    __shared__ __align__(16) __half Vt[64 * ATS];   // transposed: [dh][key]

    int qb = blockIdx.x, h = blockIdx.y, b = blockIdx.z;
    int tid = threadIdx.x;
    int w = tid >> 5, lane = tid & 31;
    int g = lane >> 2, t = lane & 3;
    size_t base = (size_t)b * TSEQ * D3;
    int hoff = h * DHEAD;

    // load Q tile [64 x 64] (half2 granularity)
    #pragma unroll
    for (int i = 0; i < 16; i++) {
        int idx = tid + i * 128;          // 0..2047 half2 slots
        int row = idx >> 5, c2 = idx & 31;
        *(__half2*)&Qs[row * ATS + c2 * 2] =
            *(const __half2*)(qkv + base + (size_t)(qb * 64 + row) * D3 + hoff + c2 * 2);
    }

    float o[8][4];
    #pragma unroll
    for (int n = 0; n < 8; n++)
        #pragma unroll
        for (int i = 0; i < 4; i++) o[n][i] = 0.f;
    float m0r = -INFINITY, m1r = -INFINITY, l0r = 0.f, l1r = 0.f;

    int rowq0 = qb * 64 + w * 16 + g;
    int rowq1 = rowq0 + 8;

    for (int kb = 0; kb <= qb; kb++) {
        __syncthreads();
        // load K [64][64] and V transposed
        #pragma unroll
        for (int i = 0; i < 16; i++) {
            int idx = tid + i * 128;
            int row = idx >> 5, c2 = idx & 31;
            size_t rowb = base + (size_t)(kb * 64 + row) * D3 + hoff;
            *(__half2*)&Ks[row * ATS + c2 * 2] = *(const __half2*)(qkv + rowb + 1024 + c2 * 2);
            __half2 v2 = *(const __half2*)(qkv + rowb + 2048 + c2 * 2);
            Vt[(c2 * 2) * ATS + row]     = __low2half(v2);
            Vt[(c2 * 2 + 1) * ATS + row] = __high2half(v2);
        }
        __syncthreads();

        // ---- S = Q K^T : 8 n8-tiles, fp32 frags ----
        float c[8][4];
        #pragma unroll
        for (int n = 0; n < 8; n++)
            #pragma unroll
            for (int i = 0; i < 4; i++) c[n][i] = 0.f;

        #pragma unroll
        for (int kc = 0; kc < 4; kc++) {
            uint32_t a[4];
            const __half* qrow0 = &Qs[(w * 16 + g) * ATS + kc * 16 + 2 * t];
            const __half* qrow1 = qrow0 + 8 * ATS;
            a[0] = *(const uint32_t*)qrow0;
            a[1] = *(const uint32_t*)qrow1;
            a[2] = *(const uint32_t*)(qrow0 + 8);
            a[3] = *(const uint32_t*)(qrow1 + 8);
            #pragma unroll
            for (int n = 0; n < 8; n++) {
                uint32_t bb[2];
                const __half* kr = &Ks[(n * 8 + g) * ATS + kc * 16 + 2 * t];
                bb[0] = *(const uint32_t*)kr;
                bb[1] = *(const uint32_t*)(kr + 8);
                mma16816(c[n], a, bb);
            }
        }

        // ---- online softmax ----
        const float sc = 0.125f;
        float smax0 = -1e30f, smax1 = -1e30f;
        #pragma unroll
        for (int n = 0; n < 8; n++) {
            int col = kb * 64 + n * 8 + 2 * t;
            c[n][0] *= sc; c[n][1] *= sc; c[n][2] *= sc; c[n][3] *= sc;
            if (kb == qb) {
                if (col     > rowq0) c[n][0] = -1e30f;
                if (col + 1 > rowq0) c[n][1] = -1e30f;
                if (col     > rowq1) c[n][2] = -1e30f;
                if (col + 1 > rowq1) c[n][3] = -1e30f;
            }
            smax0 = fmaxf(smax0, fmaxf(c[n][0], c[n][1]));
            smax1 = fmaxf(smax1, fmaxf(c[n][2], c[n][3]));
        }
        smax0 = fmaxf(smax0, __shfl_xor_sync(0xffffffffu, smax0, 1));
        smax0 = fmaxf(smax0, __shfl_xor_sync(0xffffffffu, smax0, 2));
        smax1 = fmaxf(smax1, __shfl_xor_sync(0xffffffffu, smax1, 1));
        smax1 = fmaxf(smax1, __shfl_xor_sync(0xffffffffu, smax1, 2));

        float mn0 = fmaxf(m0r, smax0), mn1 = fmaxf(m1r, smax1);
        float f0 = __expf(m0r - mn0),  f1 = __expf(m1r - mn1);
        m0r = mn0; m1r = mn1;

        float s0 = 0.f, s1 = 0.f;
        #pragma unroll
        for (int n = 0; n < 8; n++) {
            c[n][0] = __expf(c[n][0] - mn0); c[n][1] = __expf(c[n][1] - mn0);
            c[n][2] = __expf(c[n][2] - mn1); c[n][3] = __expf(c[n][3] - mn1);
            s0 += c[n][0] + c[n][1];
            s1 += c[n][2] + c[n][3];
        }
        s0 += __shfl_xor_sync(0xffffffffu, s0, 1);
        s0 += __shfl_xor_sync(0xffffffffu, s0, 2);
        s1 += __shfl_xor_sync(0xffffffffu, s1, 1);
        s1 += __shfl_xor_sync(0xffffffffu, s1, 2);
        l0r = l0r * f0 + s0;
        l1r = l1r * f1 + s1;

        #pragma unroll
        for (int n = 0; n < 8; n++) {
            o[n][0] *= f0; o[n][1] *= f0;
            o[n][2] *= f1; o[n][3] *= f1;
        }

        // ---- O += P V : pack P frags from S frags, B from Vt ----
        #pragma unroll
        for (int kc = 0; kc < 4; kc++) {
            uint32_t pa[4];
            pa[0] = pack_h2(c[2 * kc][0],     c[2 * kc][1]);
            pa[1] = pack_h2(c[2 * kc][2],     c[2 * kc][3]);
            pa[2] = pack_h2(c[2 * kc + 1][0], c[2 * kc + 1][1]);
            pa[3] = pack_h2(c[2 * kc + 1][2], c[2 * kc + 1][3]);
            #pragma unroll
            for (int n = 0; n < 8; n++) {
                uint32_t bb[2];
                const __half* vr = &Vt[(n * 8 + g) * ATS + kc * 16 + 2 * t];
                bb[0] = *(const uint32_t*)vr;
                bb[1] = *(const uint32_t*)(vr + 8);
                mma16816(o[n], pa, bb);
            }
        }
    }

    // ---- epilogue ----
    float inv0 = 1.0f / l0r, inv1 = 1.0f / l1r;
    size_t r0 = (size_t)(b * TSEQ + qb * 64 + w * 16 + g) * DMODEL + hoff;
    size_t r1 = r0 + (size_t)8 * DMODEL;
    #pragma unroll
    for (int n = 0; n < 8; n++) {
        int col = n * 8 + 2 * t;
        *(__half2*)(y + r0 + col) = __floats2half2_rn(o[n][0] * inv0, o[n][1] * inv0);
        *(__half2*)(y + r1 + col) = __floats2half2_rn(o[n][2] * inv1, o[n][3] * inv1);
    }
}

// ---------------- launch ----------------------------------------------------
template <typename T>
static T* symaddr(const void* sym) {
    void* p = nullptr;
    cudaGetSymbolAddress(&p, sym);
    return (T*)p;
}

extern "C" void kernel_launch(void* const* d_in, const int* in_sizes, int n_in,
                              void* d_out, int out_size) {
    const float* x      = (const float*)d_in[0];
    const float* ln1_w  = (const float*)d_in[1];
    const float* ln1_b  = (const float*)d_in[2];
    const float* qkv_w  = (const float*)d_in[3];
    const float* qkv_b  = (const float*)d_in[4];
    const float* out_w  = (const float*)d_in[5];
    const float* out_b  = (const float*)d_in[6];
    const float* ln2_w  = (const float*)d_in[7];
    const float* ln2_b  = (const float*)d_in[8];
    const float* mlp_w1 = (const float*)d_in[9];
    const float* mlp_b1 = (const float*)d_in[10];
    const float* mlp_w2 = (const float*)d_in[11];
    const float* mlp_b2 = (const float*)d_in[12];
    float* out = (float*)d_out;

    float*  x1   = symaddr<float>(g_x1);
    __half* qkvh = symaddr<__half>(g_qkv_h);
    __half* xlnh = symaddr<__half>(g_xln_h);
    __half* yh   = symaddr<__half>(g_y_h);
    __half* hh   = symaddr<__half>(g_h_h);
    __half* acth = symaddr<__half>(g_act_h);
    __half* wqh  = symaddr<__half>(g_wq_h);
    __half* woh  = symaddr<__half>(g_wo_h);
    __half* w1h  = symaddr<__half>(g_w1_h);
    __half* w2h  = symaddr<__half>(g_w2_h);

    cudaFuncSetAttribute(gemm_h<0,1>, cudaFuncAttributeMaxDynamicSharedMemorySize, GEMM_SMEM_H);
    cudaFuncSetAttribute(gemm_h<1,1>, cudaFuncAttributeMaxDynamicSharedMemorySize, GEMM_SMEM_H);
    cudaFuncSetAttribute(gemm_h<2,0>, cudaFuncAttributeMaxDynamicSharedMemorySize, GEMM_SMEM_H);

    // 0. weights -> half
    f2h_kernel<<<(D3 * DMODEL / 4 + 255) / 256, 256>>>((const float4*)qkv_w, (__half2*)wqh, D3 * DMODEL / 4);
    f2h_kernel<<<(DMODEL * DMODEL / 4 + 255) / 256, 256>>>((const float4*)out_w, (__half2*)woh, DMODEL * DMODEL / 4);
    f2h_kernel<<<(DFF * DMODEL / 4 + 255) / 256, 256>>>((const float4*)mlp_w1, (__half2*)w1h, DFF * DMODEL / 4);
    f2h_kernel<<<(DMODEL * DFF / 4 + 255) / 256, 256>>>((const float4*)mlp_w2, (__half2*)w2h, DMODEL * DFF / 4);

    // 1. LN1 -> half
    ln_kernel<<<MROWS, 256>>>(x, ln1_w, ln1_b, xlnh);
    // 2. QKV projection -> half qkv
    gemm_h<0,1><<<dim3(D3 / 128, MROWS / 128), 256, GEMM_SMEM_H>>>(xlnh, wqh, qkv_b, nullptr, nullptr, qkvh, D3, DMODEL);
    // 3. causal attention (fp16 mma) -> half y
    attn_h<<<dim3(TSEQ / 64, NHEAD, 2), 128>>>(qkvh, yh);
    // 4. out projection + residual -> fp32 x1
    gemm_h<2,0><<<dim3(DMODEL / 128, MROWS / 128), 256, GEMM_SMEM_H>>>(yh, woh, out_b, x, x1, nullptr, DMODEL, DMODEL);
    // 5. LN2 -> half
    ln_kernel<<<MROWS, 256>>>(x1, ln2_w, ln2_b, hh);
    // 6. MLP up + exact GELU -> half act
    gemm_h<1,1><<<dim3(DFF / 128, MROWS / 128), 256, GEMM_SMEM_H>>>(hh, w1h, mlp_b1, nullptr, nullptr, acth, DFF, DMODEL);
    // 7. MLP down + residual -> fp32 output
    gemm_h<2,0><<<dim3(DMODEL / 128, MROWS / 128), 256, GEMM_SMEM_H>>>(acth, w2h, mlp_b2, x1, out, nullptr, DMODEL, DFF);
}

// round 8
// speedup vs baseline: 6.3540x; 1.0351x over previous
#include <cuda_runtime.h>
#include <cuda_fp16.h>
#include <math.h>
#include <stdint.h>

// Problem constants
#define MROWS  4096      // B*T
#define DMODEL 1024
#define D3     3072
#define DFF    4096
#define TSEQ   2048
#define NHEAD  16
#define DHEAD  64

// ---------------- scratch (device globals: no runtime allocation) ----------
__device__ float g_x1 [(size_t)MROWS * DMODEL];
__device__ __align__(16) __half g_qkv_h[(size_t)MROWS * D3];
__device__ __align__(16) __half g_xln_h[(size_t)MROWS * DMODEL];
__device__ __align__(16) __half g_y_h  [(size_t)MROWS * DMODEL];
__device__ __align__(16) __half g_h_h  [(size_t)MROWS * DMODEL];
__device__ __align__(16) __half g_act_h[(size_t)MROWS * DFF];
__device__ __align__(16) __half g_wq_h [(size_t)D3 * DMODEL];
__device__ __align__(16) __half g_wo_h [(size_t)DMODEL * DMODEL];
__device__ __align__(16) __half g_w1_h [(size_t)DFF * DMODEL];
__device__ __align__(16) __half g_w2_h [(size_t)DMODEL * DFF];

// ---------------- helpers ---------------------------------------------------
__device__ __forceinline__ uint32_t smem_u32(const void* p) {
    uint32_t a;
    asm("{ .reg .u64 t; cvta.to.shared.u64 t, %1; cvt.u32.u64 %0, t; }" : "=r"(a) : "l"(p));
    return a;
}
__device__ __forceinline__ void cpa16(uint32_t s, const void* g) {
    asm volatile("cp.async.cg.shared.global [%0], [%1], 16;" :: "r"(s), "l"(g));
}
__device__ __forceinline__ void cp_commit() { asm volatile("cp.async.commit_group;"); }
template <int N>
__device__ __forceinline__ void cp_wait() { asm volatile("cp.async.wait_group %0;" :: "n"(N)); }

__device__ __forceinline__ void ldsm4(uint32_t& r0, uint32_t& r1, uint32_t& r2, uint32_t& r3,
                                      uint32_t addr) {
    asm volatile("ldmatrix.sync.aligned.m8n8.x4.shared.b16 {%0,%1,%2,%3}, [%4];"
                 : "=r"(r0), "=r"(r1), "=r"(r2), "=r"(r3) : "r"(addr));
}

__device__ __forceinline__ float gelu_exact(float v) {
    return 0.5f * v * (1.0f + erff(v * 0.70710678118654752f));
}

// mma.m16n8k16 fp16 -> fp32, row.col
__device__ __forceinline__ void mma16816(float* c, const uint32_t* a, const uint32_t* b) {
    asm volatile(
        "mma.sync.aligned.m16n8k16.row.col.f32.f16.f16.f32 "
        "{%0,%1,%2,%3}, {%4,%5,%6,%7}, {%8,%9}, {%0,%1,%2,%3};"
        : "+f"(c[0]), "+f"(c[1]), "+f"(c[2]), "+f"(c[3])
        : "r"(a[0]), "r"(a[1]), "r"(a[2]), "r"(a[3]), "r"(b[0]), "r"(b[1]));
}
__device__ __forceinline__ uint32_t pack_h2(float x, float y) {
    __half2 h = __floats2half2_rn(x, y);
    return *(uint32_t*)&h;
}

// ---------------- float -> half convert -------------------------------------
__global__ void f2h_kernel(const float4* __restrict__ src, __half2* __restrict__ dst, int n4) {
    int i = blockIdx.x * blockDim.x + threadIdx.x;
    if (i < n4) {
        float4 v = src[i];
        dst[2 * i]     = __floats2half2_rn(v.x, v.y);
        dst[2 * i + 1] = __floats2half2_rn(v.z, v.w);
    }
}

// ---------------- LayerNorm (fp32 in, half out) -----------------------------
__global__ void ln_kernel(const float* __restrict__ x,
                          const float* __restrict__ w,
                          const float* __restrict__ b,
                          __half* __restrict__ out) {
    int row = blockIdx.x;
    int tid = threadIdx.x;
    const float* xr = x + (size_t)row * DMODEL;

    float4 v = *(const float4*)(xr + tid * 4);
    float s  = v.x + v.y + v.z + v.w;
    float ss = v.x * v.x + v.y * v.y + v.z * v.z + v.w * v.w;

    #pragma unroll
    for (int off = 16; off >= 1; off >>= 1) {
        s  += __shfl_xor_sync(0xffffffffu, s,  off);
        ss += __shfl_xor_sync(0xffffffffu, ss, off);
    }
    __shared__ float rs[8], rss[8];
    __shared__ float stats[2];
    int wid = tid >> 5, lane = tid & 31;
    if (lane == 0) { rs[wid] = s; rss[wid] = ss; }
    __syncthreads();
    if (tid == 0) {
        float S = 0.f, SS = 0.f;
        #pragma unroll
        for (int i = 0; i < 8; i++) { S += rs[i]; SS += rss[i]; }
        float mu  = S * (1.0f / DMODEL);
        float var = SS * (1.0f / DMODEL) - mu * mu;
        stats[0] = mu;
        stats[1] = rsqrtf(var + 1e-5f);
    }
    __syncthreads();
    float mu = stats[0], r = stats[1];

    float4 wv = *(const float4*)(w + tid * 4);
    float4 bv = *(const float4*)(b + tid * 4);
    float o0 = (v.x - mu) * r * wv.x + bv.x;
    float o1 = (v.y - mu) * r * wv.y + bv.y;
    float o2 = (v.z - mu) * r * wv.z + bv.z;
    float o3 = (v.w - mu) * r * wv.w + bv.w;
    __half2* orow = (__half2*)(out + (size_t)row * DMODEL);
    orow[tid * 2]     = __floats2half2_rn(o0, o1);
    orow[tid * 2 + 1] = __floats2half2_rn(o2, o3);
}

// ---------------- fp16 GEMM NT: ldmatrix + mma, swizzled smem ----------------
// C[M,N] = A[M,K]*B[N,K]^T + bias (+epi). 128x128 tile, BK=64, 3 stages.
// smem row = 64 halves (128B), 8x16B chunks, swizzle: ch ^= row&7.
#define GK 64
#define NSTG 3
#define TILE_H (128 * 64)                 // halves per A (or B) tile
#define STG_B (2 * TILE_H * 2)            // 32768 bytes per stage
#define GEMM_SMEM (NSTG * STG_B)          // 98304 bytes

__device__ __forceinline__ uint32_t swz(int row, int ch) {   // halves offset
    return (uint32_t)(row * 64 + ((ch ^ (row & 7)) * 8));
}

template <int EPI, int HOUT>
__global__ void __launch_bounds__(256, 2)
gemm_h(const __half* __restrict__ A, const __half* __restrict__ B,
       const float* __restrict__ bias, const float* __restrict__ res,
       float* __restrict__ C, __half* __restrict__ Ch, int N, int K) {
    extern __shared__ __align__(16) __half sm[];
    uint32_t sb = smem_u32(sm);

    int tid = threadIdx.x;
    int wid = tid >> 5, lane = tid & 31;
    int g = lane >> 2, t = lane & 3;
    int bn = blockIdx.x, bm = blockIdx.y;
    int wm = wid & 3;             // m slab: 32 rows
    int wn = wid >> 2;            // n slab: 64 cols
    const int KT = K / GK;

    float acc[2][8][4];
    #pragma unroll
    for (int mt = 0; mt < 2; mt++)
        #pragma unroll
        for (int n = 0; n < 8; n++)
            #pragma unroll
            for (int i = 0; i < 4; i++) acc[mt][n][i] = 0.f;

    const __half* Ab = A + (size_t)(bm * 128) * K;
    const __half* Bb = B + (size_t)(bn * 128) * K;

    // per stage: A 1024 chunks + B 1024 chunks; 8 cpa16 per thread
    auto issue = [&](int kt) {
        uint32_t dst = sb + (uint32_t)(kt % NSTG) * STG_B;
        #pragma unroll
        for (int i = 0; i < 4; i++) {
            int c = i * 256 + tid;          // 0..1023
            int row = c >> 3, ch = c & 7;
            cpa16(dst + swz(row, ch) * 2,             Ab + (size_t)row * K + kt * GK + ch * 8);
            cpa16(dst + TILE_H * 2 + swz(row, ch) * 2, Bb + (size_t)row * K + kt * GK + ch * 8);
        }
    };

    issue(0); cp_commit();
    issue(1); cp_commit();

    for (int kt = 0; kt < KT; kt++) {
        bool more = (kt + 2 < KT);
        if (more) cp_wait<1>();
        else      cp_wait<0>();
        __syncthreads();
        if (more) { issue(kt + 2); cp_commit(); }

        uint32_t stA = sb + (uint32_t)(kt % NSTG) * STG_B;
        uint32_t stB = stA + TILE_H * 2;

        #pragma unroll
        for (int kk = 0; kk < 4; kk++) {      // 4 k16 steps
            // A frags: 2 m16 tiles
            uint32_t a[2][4];
            #pragma unroll
            for (int mt = 0; mt < 2; mt++) {
                int row = wm * 32 + mt * 16 + (lane & 7) + ((lane >> 3) & 1) * 8;
                int ch  = kk * 2 + (lane >> 4);
                ldsm4(a[mt][0], a[mt][1], a[mt][2], a[mt][3], stA + swz(row, ch) * 2);
            }
            // B frags: 4 ldsm.x4, each covers 2 n8 tiles
            uint32_t bfr[8][2];
            #pragma unroll
            for (int np = 0; np < 4; np++) {
                uint32_t r0, r1, r2, r3;
                int row = wn * 64 + np * 16 + (lane & 7) + ((lane >> 3) & 1) * 8;
                int ch  = kk * 2 + (lane >> 4);
                ldsm4(r0, r1, r2, r3, stB + swz(row, ch) * 2);
                bfr[np * 2][0]     = r0; bfr[np * 2][1]     = r2;
                bfr[np * 2 + 1][0] = r1; bfr[np * 2 + 1][1] = r3;
            }
            #pragma unroll
            for (int mt = 0; mt < 2; mt++)
                #pragma unroll
                for (int n = 0; n < 8; n++)
                    mma16816(acc[mt][n], a[mt], bfr[n]);
        }
    }

    // ---- epilogue: stage C through smem ----
    __syncthreads();
    float* Cs = (float*)sm;   // [128][132] floats = 67584 B < 98304
    #pragma unroll
    for (int mt = 0; mt < 2; mt++)
        #pragma unroll
        for (int n = 0; n < 8; n++) {
            int r0 = wm * 32 + mt * 16 + g;
            int c0 = wn * 64 + n * 8 + 2 * t;
            Cs[r0 * 132 + c0]           = acc[mt][n][0];
            Cs[r0 * 132 + c0 + 1]       = acc[mt][n][1];
            Cs[(r0 + 8) * 132 + c0]     = acc[mt][n][2];
            Cs[(r0 + 8) * 132 + c0 + 1] = acc[mt][n][3];
        }
    __syncthreads();

    int m0 = bm * 128, n0 = bn * 128;
    #pragma unroll
    for (int it = 0; it < 16; it++) {
        int idx = tid + it * 256;
        int r  = idx >> 5;
        int c4 = (idx & 31) * 4;
        float4 v = *(const float4*)&Cs[r * 132 + c4];
        float4 bv = *(const float4*)(bias + n0 + c4);
        v.x += bv.x; v.y += bv.y; v.z += bv.z; v.w += bv.w;
        if (EPI == 1) {
            v.x = gelu_exact(v.x); v.y = gelu_exact(v.y);
            v.z = gelu_exact(v.z); v.w = gelu_exact(v.w);
        }
        size_t off = (size_t)(m0 + r) * N + n0 + c4;
        if (EPI == 2) {
            float4 rv = *(const float4*)(res + off);
            v.x += rv.x; v.y += rv.y; v.z += rv.z; v.w += rv.w;
        }
        if (HOUT) {
            __half2* hp = (__half2*)(Ch + off);
            hp[0] = __floats2half2_rn(v.x, v.y);
            hp[1] = __floats2half2_rn(v.z, v.w);
        } else {
            *(float4*)(C + off) = v;
        }
    }
}

// ---------------- FA2-style fp16 attention ----------------------------------
#define ATS 72    // smem stride (halves)

__global__ void __launch_bounds__(128)
attn_h(const __half* __restrict__ qkv, __half* __restrict__ y) {
    __shared__ __align__(16) __half Qs[64 * ATS];
    __shared__ __align__(16) __half Ks[64 * ATS];
    __shared__ __align__(16) __half Vt[64 * ATS];   // transposed: [dh][key]

    int qb = blockIdx.x, h = blockIdx.y, b = blockIdx.z;
    int tid = threadIdx.x;
    int w = tid >> 5, lane = tid & 31;
    int g = lane >> 2, t = lane & 3;
    size_t base = (size_t)b * TSEQ * D3;
    int hoff = h * DHEAD;

    #pragma unroll
    for (int i = 0; i < 16; i++) {
        int idx = tid + i * 128;
        int row = idx >> 5, c2 = idx & 31;
        *(__half2*)&Qs[row * ATS + c2 * 2] =
            *(const __half2*)(qkv + base + (size_t)(qb * 64 + row) * D3 + hoff + c2 * 2);
    }

    float o[8][4];
    #pragma unroll
    for (int n = 0; n < 8; n++)
        #pragma unroll
        for (int i = 0; i < 4; i++) o[n][i] = 0.f;
    float m0r = -INFINITY, m1r = -INFINITY, l0r = 0.f, l1r = 0.f;

    int rowq0 = qb * 64 + w * 16 + g;
    int rowq1 = rowq0 + 8;

    for (int kb = 0; kb <= qb; kb++) {
        __syncthreads();
        #pragma unroll
        for (int i = 0; i < 16; i++) {
            int idx = tid + i * 128;
            int row = idx >> 5, c2 = idx & 31;
            size_t rowb = base + (size_t)(kb * 64 + row) * D3 + hoff;
            *(__half2*)&Ks[row * ATS + c2 * 2] = *(const __half2*)(qkv + rowb + 1024 + c2 * 2);
            __half2 v2 = *(const __half2*)(qkv + rowb + 2048 + c2 * 2);
            Vt[(c2 * 2) * ATS + row]     = __low2half(v2);
            Vt[(c2 * 2 + 1) * ATS + row] = __high2half(v2);
        }
        __syncthreads();

        float c[8][4];
        #pragma unroll
        for (int n = 0; n < 8; n++)
            #pragma unroll
            for (int i = 0; i < 4; i++) c[n][i] = 0.f;

        #pragma unroll
        for (int kc = 0; kc < 4; kc++) {
            uint32_t a[4];
            const __half* qrow0 = &Qs[(w * 16 + g) * ATS + kc * 16 + 2 * t];
            const __half* qrow1 = qrow0 + 8 * ATS;
            a[0] = *(const uint32_t*)qrow0;
            a[1] = *(const uint32_t*)qrow1;
            a[2] = *(const uint32_t*)(qrow0 + 8);
            a[3] = *(const uint32_t*)(qrow1 + 8);
            #pragma unroll
            for (int n = 0; n < 8; n++) {
                uint32_t bb[2];
                const __half* kr = &Ks[(n * 8 + g) * ATS + kc * 16 + 2 * t];
                bb[0] = *(const uint32_t*)kr;
                bb[1] = *(const uint32_t*)(kr + 8);
                mma16816(c[n], a, bb);
            }
        }

        const float sc = 0.125f;
        float smax0 = -1e30f, smax1 = -1e30f;
        #pragma unroll
        for (int n = 0; n < 8; n++) {
            int col = kb * 64 + n * 8 + 2 * t;
            c[n][0] *= sc; c[n][1] *= sc; c[n][2] *= sc; c[n][3] *= sc;
            if (kb == qb) {
                if (col     > rowq0) c[n][0] = -1e30f;
                if (col + 1 > rowq0) c[n][1] = -1e30f;
                if (col     > rowq1) c[n][2] = -1e30f;
                if (col + 1 > rowq1) c[n][3] = -1e30f;
            }
            smax0 = fmaxf(smax0, fmaxf(c[n][0], c[n][1]));
            smax1 = fmaxf(smax1, fmaxf(c[n][2], c[n][3]));
        }
        smax0 = fmaxf(smax0, __shfl_xor_sync(0xffffffffu, smax0, 1));
        smax0 = fmaxf(smax0, __shfl_xor_sync(0xffffffffu, smax0, 2));
        smax1 = fmaxf(smax1, __shfl_xor_sync(0xffffffffu, smax1, 1));
        smax1 = fmaxf(smax1, __shfl_xor_sync(0xffffffffu, smax1, 2));

        float mn0 = fmaxf(m0r, smax0), mn1 = fmaxf(m1r, smax1);
        float f0 = __expf(m0r - mn0),  f1 = __expf(m1r - mn1);
        m0r = mn0; m1r = mn1;

        float s0 = 0.f, s1 = 0.f;
        #pragma unroll
        for (int n = 0; n < 8; n++) {
            c[n][0] = __expf(c[n][0] - mn0); c[n][1] = __expf(c[n][1] - mn0);
            c[n][2] = __expf(c[n][2] - mn1); c[n][3] = __expf(c[n][3] - mn1);
            s0 += c[n][0] + c[n][1];
            s1 += c[n][2] + c[n][3];
        }
        s0 += __shfl_xor_sync(0xffffffffu, s0, 1);
        s0 += __shfl_xor_sync(0xffffffffu, s0, 2);
        s1 += __shfl_xor_sync(0xffffffffu, s1, 1);
        s1 += __shfl_xor_sync(0xffffffffu, s1, 2);
        l0r = l0r * f0 + s0;
        l1r = l1r * f1 + s1;

        #pragma unroll
        for (int n = 0; n < 8; n++) {
            o[n][0] *= f0; o[n][1] *= f0;
            o[n][2] *= f1; o[n][3] *= f1;
        }

        #pragma unroll
        for (int kc = 0; kc < 4; kc++) {
            uint32_t pa[4];
            pa[0] = pack_h2(c[2 * kc][0],     c[2 * kc][1]);
            pa[1] = pack_h2(c[2 * kc][2],     c[2 * kc][3]);
            pa[2] = pack_h2(c[2 * kc + 1][0], c[2 * kc + 1][1]);
            pa[3] = pack_h2(c[2 * kc + 1][2], c[2 * kc + 1][3]);
            #pragma unroll
            for (int n = 0; n < 8; n++) {
                uint32_t bb[2];
                const __half* vr = &Vt[(n * 8 + g) * ATS + kc * 16 + 2 * t];
                bb[0] = *(const uint32_t*)vr;
                bb[1] = *(const uint32_t*)(vr + 8);
                mma16816(o[n], pa, bb);
            }
        }
    }

    float inv0 = 1.0f / l0r, inv1 = 1.0f / l1r;
    size_t r0 = (size_t)(b * TSEQ + qb * 64 + w * 16 + g) * DMODEL + hoff;
    size_t r1 = r0 + (size_t)8 * DMODEL;
    #pragma unroll
    for (int n = 0; n < 8; n++) {
        int col = n * 8 + 2 * t;
        *(__half2*)(y + r0 + col) = __floats2half2_rn(o[n][0] * inv0, o[n][1] * inv0);
        *(__half2*)(y + r1 + col) = __floats2half2_rn(o[n][2] * inv1, o[n][3] * inv1);
    }
}

// ---------------- launch ----------------------------------------------------
template <typename T>
static T* symaddr(const void* sym) {
    void* p = nullptr;
    cudaGetSymbolAddress(&p, sym);
    return (T*)p;
}

extern "C" void kernel_launch(void* const* d_in, const int* in_sizes, int n_in,
                              void* d_out, int out_size) {
    const float* x      = (const float*)d_in[0];
    const float* ln1_w  = (const float*)d_in[1];
    const float* ln1_b  = (const float*)d_in[2];
    const float* qkv_w  = (const float*)d_in[3];
    const float* qkv_b  = (const float*)d_in[4];
    const float* out_w  = (const float*)d_in[5];
    const float* out_b  = (const float*)d_in[6];
    const float* ln2_w  = (const float*)d_in[7];
    const float* ln2_b  = (const float*)d_in[8];
    const float* mlp_w1 = (const float*)d_in[9];
    const float* mlp_b1 = (const float*)d_in[10];
    const float* mlp_w2 = (const float*)d_in[11];
    const float* mlp_b2 = (const float*)d_in[12];
    float* out = (float*)d_out;

    float*  x1   = symaddr<float>(g_x1);
    __half* qkvh = symaddr<__half>(g_qkv_h);
    __half* xlnh = symaddr<__half>(g_xln_h);
    __half* yh   = symaddr<__half>(g_y_h);
    __half* hh   = symaddr<__half>(g_h_h);
    __half* acth = symaddr<__half>(g_act_h);
    __half* wqh  = symaddr<__half>(g_wq_h);
    __half* woh  = symaddr<__half>(g_wo_h);
    __half* w1h  = symaddr<__half>(g_w1_h);
    __half* w2h  = symaddr<__half>(g_w2_h);

    cudaFuncSetAttribute(gemm_h<0,1>, cudaFuncAttributeMaxDynamicSharedMemorySize, GEMM_SMEM);
    cudaFuncSetAttribute(gemm_h<1,1>, cudaFuncAttributeMaxDynamicSharedMemorySize, GEMM_SMEM);
    cudaFuncSetAttribute(gemm_h<2,0>, cudaFuncAttributeMaxDynamicSharedMemorySize, GEMM_SMEM);

    // 0. weights -> half
    f2h_kernel<<<(D3 * DMODEL / 4 + 255) / 256, 256>>>((const float4*)qkv_w, (__half2*)wqh, D3 * DMODEL / 4);
    f2h_kernel<<<(DMODEL * DMODEL / 4 + 255) / 256, 256>>>((const float4*)out_w, (__half2*)woh, DMODEL * DMODEL / 4);
    f2h_kernel<<<(DFF * DMODEL / 4 + 255) / 256, 256>>>((const float4*)mlp_w1, (__half2*)w1h, DFF * DMODEL / 4);
    f2h_kernel<<<(DMODEL * DFF / 4 + 255) / 256, 256>>>((const float4*)mlp_w2, (__half2*)w2h, DMODEL * DFF / 4);

    // 1. LN1 -> half
    ln_kernel<<<MROWS, 256>>>(x, ln1_w, ln1_b, xlnh);
    // 2. QKV projection -> half qkv
    gemm_h<0,1><<<dim3(D3 / 128, MROWS / 128), 256, GEMM_SMEM>>>(xlnh, wqh, qkv_b, nullptr, nullptr, qkvh, D3, DMODEL);
    // 3. causal attention (fp16 mma) -> half y
    attn_h<<<dim3(TSEQ / 64, NHEAD, 2), 128>>>(qkvh, yh);
    // 4. out projection + residual -> fp32 x1
    gemm_h<2,0><<<dim3(DMODEL / 128, MROWS / 128), 256, GEMM_SMEM>>>(yh, woh, out_b, x, x1, nullptr, DMODEL, DMODEL);
    // 5. LN2 -> half
    ln_kernel<<<MROWS, 256>>>(x1, ln2_w, ln2_b, hh);
    // 6. MLP up + exact GELU -> half act
    gemm_h<1,1><<<dim3(DFF / 128, MROWS / 128), 256, GEMM_SMEM>>>(hh, w1h, mlp_b1, nullptr, nullptr, acth, DFF, DMODEL);
    // 7. MLP down + residual -> fp32 output
    gemm_h<2,0><<<dim3(DMODEL / 128, MROWS / 128), 256, GEMM_SMEM>>>(acth, w2h, mlp_b2, x1, out, nullptr, DMODEL, DFF);
}

// round 9
// speedup vs baseline: 7.4774x; 1.1768x over previous
#include <cuda_runtime.h>
#include <cuda_fp16.h>
#include <math.h>
#include <stdint.h>

// Problem constants
#define MROWS  4096      // B*T
#define DMODEL 1024
#define D3     3072
#define DFF    4096
#define TSEQ   2048
#define NHEAD  16
#define DHEAD  64

// ---------------- scratch (device globals: no runtime allocation) ----------
__device__ float g_x1 [(size_t)MROWS * DMODEL];
__device__ __align__(16) __half g_qkv_h[(size_t)MROWS * D3];
__device__ __align__(16) __half g_xln_h[(size_t)MROWS * DMODEL];
__device__ __align__(16) __half g_y_h  [(size_t)MROWS * DMODEL];
__device__ __align__(16) __half g_h_h  [(size_t)MROWS * DMODEL];
__device__ __align__(16) __half g_act_h[(size_t)MROWS * DFF];
__device__ __align__(16) __half g_wq_h [(size_t)D3 * DMODEL];
__device__ __align__(16) __half g_wo_h [(size_t)DMODEL * DMODEL];
__device__ __align__(16) __half g_w1_h [(size_t)DFF * DMODEL];
__device__ __align__(16) __half g_w2_h [(size_t)DMODEL * DFF];

// ---------------- helpers ---------------------------------------------------
__device__ __forceinline__ uint32_t smem_u32(const void* p) {
    uint32_t a;
    asm("{ .reg .u64 t; cvta.to.shared.u64 t, %1; cvt.u32.u64 %0, t; }" : "=r"(a) : "l"(p));
    return a;
}
__device__ __forceinline__ void cpa16(uint32_t s, const void* g) {
    asm volatile("cp.async.cg.shared.global [%0], [%1], 16;" :: "r"(s), "l"(g));
}
__device__ __forceinline__ void cp_commit() { asm volatile("cp.async.commit_group;"); }
template <int N>
__device__ __forceinline__ void cp_wait() { asm volatile("cp.async.wait_group %0;" :: "n"(N)); }

__device__ __forceinline__ void ldsm4(uint32_t& r0, uint32_t& r1, uint32_t& r2, uint32_t& r3,
                                      uint32_t addr) {
    asm volatile("ldmatrix.sync.aligned.m8n8.x4.shared.b16 {%0,%1,%2,%3}, [%4];"
                 : "=r"(r0), "=r"(r1), "=r"(r2), "=r"(r3) : "r"(addr));
}
__device__ __forceinline__ void ldsm4t(uint32_t& r0, uint32_t& r1, uint32_t& r2, uint32_t& r3,
                                       uint32_t addr) {
    asm volatile("ldmatrix.sync.aligned.m8n8.x4.trans.shared.b16 {%0,%1,%2,%3}, [%4];"
                 : "=r"(r0), "=r"(r1), "=r"(r2), "=r"(r3) : "r"(addr));
}

__device__ __forceinline__ float gelu_exact(float v) {
    return 0.5f * v * (1.0f + erff(v * 0.70710678118654752f));
}

// mma.m16n8k16 fp16 -> fp32, row.col
__device__ __forceinline__ void mma16816(float* c, const uint32_t* a, const uint32_t* b) {
    asm volatile(
        "mma.sync.aligned.m16n8k16.row.col.f32.f16.f16.f32 "
        "{%0,%1,%2,%3}, {%4,%5,%6,%7}, {%8,%9}, {%0,%1,%2,%3};"
        : "+f"(c[0]), "+f"(c[1]), "+f"(c[2]), "+f"(c[3])
        : "r"(a[0]), "r"(a[1]), "r"(a[2]), "r"(a[3]), "r"(b[0]), "r"(b[1]));
}
__device__ __forceinline__ uint32_t pack_h2(float x, float y) {
    __half2 h = __floats2half2_rn(x, y);
    return *(uint32_t*)&h;
}

// ---------------- float -> half convert (2 float4 per thread) ---------------
__global__ void f2h_kernel(const float4* __restrict__ src, __half2* __restrict__ dst, int n4) {
    int half_n = n4 >> 1;
    int i = blockIdx.x * blockDim.x + threadIdx.x;
    if (i < half_n) {
        float4 v0 = src[i];
        float4 v1 = src[i + half_n];
        dst[2 * i]     = __floats2half2_rn(v0.x, v0.y);
        dst[2 * i + 1] = __floats2half2_rn(v0.z, v0.w);
        dst[2 * (i + half_n)]     = __floats2half2_rn(v1.x, v1.y);
        dst[2 * (i + half_n) + 1] = __floats2half2_rn(v1.z, v1.w);
    }
}

// ---------------- LayerNorm (fp32 in, half out) -----------------------------
__global__ void ln_kernel(const float* __restrict__ x,
                          const float* __restrict__ w,
                          const float* __restrict__ b,
                          __half* __restrict__ out) {
    int row = blockIdx.x;
    int tid = threadIdx.x;
    const float* xr = x + (size_t)row * DMODEL;

    float4 v = *(const float4*)(xr + tid * 4);
    float s  = v.x + v.y + v.z + v.w;
    float ss = v.x * v.x + v.y * v.y + v.z * v.z + v.w * v.w;

    #pragma unroll
    for (int off = 16; off >= 1; off >>= 1) {
        s  += __shfl_xor_sync(0xffffffffu, s,  off);
        ss += __shfl_xor_sync(0xffffffffu, ss, off);
    }
    __shared__ float rs[8], rss[8];
    __shared__ float stats[2];
    int wid = tid >> 5, lane = tid & 31;
    if (lane == 0) { rs[wid] = s; rss[wid] = ss; }
    __syncthreads();
    if (tid == 0) {
        float S = 0.f, SS = 0.f;
        #pragma unroll
        for (int i = 0; i < 8; i++) { S += rs[i]; SS += rss[i]; }
        float mu  = S * (1.0f / DMODEL);
        float var = SS * (1.0f / DMODEL) - mu * mu;
        stats[0] = mu;
        stats[1] = rsqrtf(var + 1e-5f);
    }
    __syncthreads();
    float mu = stats[0], r = stats[1];

    float4 wv = *(const float4*)(w + tid * 4);
    float4 bv = *(const float4*)(b + tid * 4);
    float o0 = (v.x - mu) * r * wv.x + bv.x;
    float o1 = (v.y - mu) * r * wv.y + bv.y;
    float o2 = (v.z - mu) * r * wv.z + bv.z;
    float o3 = (v.w - mu) * r * wv.w + bv.w;
    __half2* orow = (__half2*)(out + (size_t)row * DMODEL);
    orow[tid * 2]     = __floats2half2_rn(o0, o1);
    orow[tid * 2 + 1] = __floats2half2_rn(o2, o3);
}

// ---------------- fp16 GEMM NT: ldmatrix + mma, swizzled smem ----------------
// (unchanged from round 8 — at the legacy-HMMA ceiling; do not touch)
#define GK 64
#define NSTG 3
#define TILE_H (128 * 64)
#define STG_B (2 * TILE_H * 2)
#define GEMM_SMEM (NSTG * STG_B)          // 98304 bytes

__device__ __forceinline__ uint32_t swz(int row, int ch) {
    return (uint32_t)(row * 64 + ((ch ^ (row & 7)) * 8));
}

template <int EPI, int HOUT>
__global__ void __launch_bounds__(256, 2)
gemm_h(const __half* __restrict__ A, const __half* __restrict__ B,
       const float* __restrict__ bias, const float* __restrict__ res,
       float* __restrict__ C, __half* __restrict__ Ch, int N, int K) {
    extern __shared__ __align__(16) __half sm[];
    uint32_t sb = smem_u32(sm);

    int tid = threadIdx.x;
    int wid = tid >> 5, lane = tid & 31;
    int g = lane >> 2, t = lane & 3;
    int bn = blockIdx.x, bm = blockIdx.y;
    int wm = wid & 3;
    int wn = wid >> 2;
    const int KT = K / GK;

    float acc[2][8][4];
    #pragma unroll
    for (int mt = 0; mt < 2; mt++)
        #pragma unroll
        for (int n = 0; n < 8; n++)
            #pragma unroll
            for (int i = 0; i < 4; i++) acc[mt][n][i] = 0.f;

    const __half* Ab = A + (size_t)(bm * 128) * K;
    const __half* Bb = B + (size_t)(bn * 128) * K;

    auto issue = [&](int kt) {
        uint32_t dst = sb + (uint32_t)(kt % NSTG) * STG_B;
        #pragma unroll
        for (int i = 0; i < 4; i++) {
            int c = i * 256 + tid;
            int row = c >> 3, ch = c & 7;
            cpa16(dst + swz(row, ch) * 2,              Ab + (size_t)row * K + kt * GK + ch * 8);
            cpa16(dst + TILE_H * 2 + swz(row, ch) * 2, Bb + (size_t)row * K + kt * GK + ch * 8);
        }
    };

    issue(0); cp_commit();
    issue(1); cp_commit();

    for (int kt = 0; kt < KT; kt++) {
        bool more = (kt + 2 < KT);
        if (more) cp_wait<1>();
        else      cp_wait<0>();
        __syncthreads();
        if (more) { issue(kt + 2); cp_commit(); }

        uint32_t stA = sb + (uint32_t)(kt % NSTG) * STG_B;
        uint32_t stB = stA + TILE_H * 2;

        #pragma unroll
        for (int kk = 0; kk < 4; kk++) {
            uint32_t a[2][4];
            #pragma unroll
            for (int mt = 0; mt < 2; mt++) {
                int row = wm * 32 + mt * 16 + (lane & 7) + ((lane >> 3) & 1) * 8;
                int ch  = kk * 2 + (lane >> 4);
                ldsm4(a[mt][0], a[mt][1], a[mt][2], a[mt][3], stA + swz(row, ch) * 2);
            }
            uint32_t bfr[8][2];
            #pragma unroll
            for (int np = 0; np < 4; np++) {
                uint32_t r0, r1, r2, r3;
                int row = wn * 64 + np * 16 + (lane & 7) + ((lane >> 3) & 1) * 8;
                int ch  = kk * 2 + (lane >> 4);
                ldsm4(r0, r1, r2, r3, stB + swz(row, ch) * 2);
                bfr[np * 2][0]     = r0; bfr[np * 2][1]     = r2;
                bfr[np * 2 + 1][0] = r1; bfr[np * 2 + 1][1] = r3;
            }
            #pragma unroll
            for (int mt = 0; mt < 2; mt++)
                #pragma unroll
                for (int n = 0; n < 8; n++)
                    mma16816(acc[mt][n], a[mt], bfr[n]);
        }
    }

    __syncthreads();
    float* Cs = (float*)sm;
    #pragma unroll
    for (int mt = 0; mt < 2; mt++)
        #pragma unroll
        for (int n = 0; n < 8; n++) {
            int r0 = wm * 32 + mt * 16 + g;
            int c0 = wn * 64 + n * 8 + 2 * t;
            Cs[r0 * 132 + c0]           = acc[mt][n][0];
            Cs[r0 * 132 + c0 + 1]       = acc[mt][n][1];
            Cs[(r0 + 8) * 132 + c0]     = acc[mt][n][2];
            Cs[(r0 + 8) * 132 + c0 + 1] = acc[mt][n][3];
        }
    __syncthreads();

    int m0 = bm * 128, n0 = bn * 128;
    #pragma unroll
    for (int it = 0; it < 16; it++) {
        int idx = tid + it * 256;
        int r  = idx >> 5;
        int c4 = (idx & 31) * 4;
        float4 v = *(const float4*)&Cs[r * 132 + c4];
        float4 bv = *(const float4*)(bias + n0 + c4);
        v.x += bv.x; v.y += bv.y; v.z += bv.z; v.w += bv.w;
        if (EPI == 1) {
            v.x = gelu_exact(v.x); v.y = gelu_exact(v.y);
            v.z = gelu_exact(v.z); v.w = gelu_exact(v.w);
        }
        size_t off = (size_t)(m0 + r) * N + n0 + c4;
        if (EPI == 2) {
            float4 rv = *(const float4*)(res + off);
            v.x += rv.x; v.y += rv.y; v.z += rv.z; v.w += rv.w;
        }
        if (HOUT) {
            __half2* hp = (__half2*)(Ch + off);
            hp[0] = __floats2half2_rn(v.x, v.y);
            hp[1] = __floats2half2_rn(v.z, v.w);
        } else {
            *(float4*)(C + off) = v;
        }
    }
}

// ---------------- FA2 fp16 attention: ldmatrix + cp.async double buffer -----
// grid (T/64, H, B), 4 warps. Q frags in registers (pre-scaled by 1/8).
// K row-major smem -> ldsm4 (B frags). V row-major smem -> ldsm4.trans.
#define ATS 72    // smem stride in halves (144B rows: conflict-free ldsm)

__global__ void __launch_bounds__(128)
attn_h(const __half* __restrict__ qkv, __half* __restrict__ y) {
    __shared__ __align__(16) __half Qs[64 * ATS];
    __shared__ __align__(16) __half KV[2][2][64 * ATS];   // [stage][K/V][row][col]

    int qb = blockIdx.x, h = blockIdx.y, b = blockIdx.z;
    int tid = threadIdx.x;
    int w = tid >> 5, lane = tid & 31;
    int g = lane >> 2, t = lane & 3;
    size_t base = (size_t)b * TSEQ * D3;
    int hoff = h * DHEAD;

    uint32_t sbKV = smem_u32(&KV[0][0][0]);

    // stage load: K tile + V tile, 1024 x 16B chunks, 8 per thread
    auto loadKV = [&](int kb, int st) {
        #pragma unroll
        for (int i = 0; i < 8; i++) {
            int idx = tid + i * 128;            // 0..1023
            int isV = idx >> 9;                 // 0: K, 1: V
            int row = (idx >> 3) & 63;
            int ch  = idx & 7;
            const __half* src = qkv + base + (size_t)(kb * 64 + row) * D3 + hoff
                               + 1024 + isV * 1024 + ch * 8;
            cpa16(sbKV + (uint32_t)(((st * 2 + isV) * 64 + row) * ATS + ch * 8) * 2, src);
        }
    };

    // load Q tile (half2 stores) + prefetch KV(0)
    #pragma unroll
    for (int i = 0; i < 16; i++) {
        int idx = tid + i * 128;
        int row = idx >> 5, c2 = idx & 31;
        *(__half2*)&Qs[row * ATS + c2 * 2] =
            *(const __half2*)(qkv + base + (size_t)(qb * 64 + row) * D3 + hoff + c2 * 2);
    }
    loadKV(0, 0); cp_commit();
    __syncthreads();

    // Q fragments, pre-scaled by 1/8 (exact in half)
    uint32_t qf[4][4];
    const __half2 hsc = __floats2half2_rn(0.125f, 0.125f);
    #pragma unroll
    for (int kc = 0; kc < 4; kc++) {
        int row = w * 16 + (lane & 7) + ((lane >> 3) & 1) * 8;
        int col = kc * 16 + (lane >> 4) * 8;
        ldsm4(qf[kc][0], qf[kc][1], qf[kc][2], qf[kc][3],
              smem_u32(&Qs[row * ATS + col]));
        #pragma unroll
        for (int i = 0; i < 4; i++) {
            __half2 v = __hmul2(*(__half2*)&qf[kc][i], hsc);
            qf[kc][i] = *(uint32_t*)&v;
        }
    }

    float o[8][4];
    #pragma unroll
    for (int n = 0; n < 8; n++)
        #pragma unroll
        for (int i = 0; i < 4; i++) o[n][i] = 0.f;
    float m0r = -INFINITY, m1r = -INFINITY, l0r = 0.f, l1r = 0.f;

    int rowq0 = qb * 64 + w * 16 + g;
    int rowq1 = rowq0 + 8;

    for (int kb = 0; kb <= qb; kb++) {
        int st = kb & 1;
        if (kb < qb) { loadKV(kb + 1, st ^ 1); cp_commit(); cp_wait<1>(); }
        else         { cp_wait<0>(); }
        __syncthreads();                       // stage st visible to all

        uint32_t stK = sbKV + (uint32_t)((st * 2) * 64 * ATS) * 2;
        uint32_t stV = sbKV + (uint32_t)((st * 2 + 1) * 64 * ATS) * 2;

        // ---- S = (Q/8) K^T ----
        float c[8][4];
        #pragma unroll
        for (int n = 0; n < 8; n++)
            #pragma unroll
            for (int i = 0; i < 4; i++) c[n][i] = 0.f;

        #pragma unroll
        for (int kc = 0; kc < 4; kc++) {
            #pragma unroll
            for (int n16 = 0; n16 < 4; n16++) {
                uint32_t r0, r1, r2, r3;
                int row = n16 * 16 + (lane & 7) + ((lane >> 3) & 1) * 8;
                int col = kc * 16 + (lane >> 4) * 8;
                ldsm4(r0, r1, r2, r3, stK + (uint32_t)(row * ATS + col) * 2);
                uint32_t b0[2] = {r0, r2}, b1[2] = {r1, r3};
                mma16816(c[2 * n16],     qf[kc], b0);
                mma16816(c[2 * n16 + 1], qf[kc], b1);
            }
        }

        // ---- online softmax (S already scaled) ----
        float smax0 = -1e30f, smax1 = -1e30f;
        #pragma unroll
        for (int n = 0; n < 8; n++) {
            int col = kb * 64 + n * 8 + 2 * t;
            if (kb == qb) {
                if (col     > rowq0) c[n][0] = -1e30f;
                if (col + 1 > rowq0) c[n][1] = -1e30f;
                if (col     > rowq1) c[n][2] = -1e30f;
                if (col + 1 > rowq1) c[n][3] = -1e30f;
            }
            smax0 = fmaxf(smax0, fmaxf(c[n][0], c[n][1]));
            smax1 = fmaxf(smax1, fmaxf(c[n][2], c[n][3]));
        }
        smax0 = fmaxf(smax0, __shfl_xor_sync(0xffffffffu, smax0, 1));
        smax0 = fmaxf(smax0, __shfl_xor_sync(0xffffffffu, smax0, 2));
        smax1 = fmaxf(smax1, __shfl_xor_sync(0xffffffffu, smax1, 1));
        smax1 = fmaxf(smax1, __shfl_xor_sync(0xffffffffu, smax1, 2));

        float mn0 = fmaxf(m0r, smax0), mn1 = fmaxf(m1r, smax1);
        float f0 = __expf(m0r - mn0),  f1 = __expf(m1r - mn1);
        m0r = mn0; m1r = mn1;

        float s0 = 0.f, s1 = 0.f;
        #pragma unroll
        for (int n = 0; n < 8; n++) {
            c[n][0] = __expf(c[n][0] - mn0); c[n][1] = __expf(c[n][1] - mn0);
            c[n][2] = __expf(c[n][2] - mn1); c[n][3] = __expf(c[n][3] - mn1);
            s0 += c[n][0] + c[n][1];
            s1 += c[n][2] + c[n][3];
        }
        s0 += __shfl_xor_sync(0xffffffffu, s0, 1);
        s0 += __shfl_xor_sync(0xffffffffu, s0, 2);
        s1 += __shfl_xor_sync(0xffffffffu, s1, 1);
        s1 += __shfl_xor_sync(0xffffffffu, s1, 2);
        l0r = l0r * f0 + s0;
        l1r = l1r * f1 + s1;

        #pragma unroll
        for (int n = 0; n < 8; n++) {
            o[n][0] *= f0; o[n][1] *= f0;
            o[n][2] *= f1; o[n][3] *= f1;
        }

        // ---- O += P V : V B-frags via ldmatrix.trans ----
        #pragma unroll
        for (int kc = 0; kc < 4; kc++) {
            uint32_t pa[4];
            pa[0] = pack_h2(c[2 * kc][0],     c[2 * kc][1]);
            pa[1] = pack_h2(c[2 * kc][2],     c[2 * kc][3]);
            pa[2] = pack_h2(c[2 * kc + 1][0], c[2 * kc + 1][1]);
            pa[3] = pack_h2(c[2 * kc + 1][2], c[2 * kc + 1][3]);
            #pragma unroll
            for (int d16 = 0; d16 < 4; d16++) {
                uint32_t r0, r1, r2, r3;
                int m = lane >> 3;          // mat index 0..3
                int row = kc * 16 + (m & 1) * 8 + (lane & 7);
                int col = d16 * 16 + (m >> 1) * 8;
                ldsm4t(r0, r1, r2, r3, stV + (uint32_t)(row * ATS + col) * 2);
                uint32_t b0[2] = {r0, r1}, b1[2] = {r2, r3};
                mma16816(o[2 * d16],     pa, b0);
                mma16816(o[2 * d16 + 1], pa, b1);
            }
        }
        __syncthreads();   // all reads of stage st done before it is reloaded
    }

    // ---- epilogue ----
    float inv0 = 1.0f / l0r, inv1 = 1.0f / l1r;
    size_t r0 = (size_t)(b * TSEQ + qb * 64 + w * 16 + g) * DMODEL + hoff;
    size_t r1 = r0 + (size_t)8 * DMODEL;
    #pragma unroll
    for (int n = 0; n < 8; n++) {
        int col = n * 8 + 2 * t;
        *(__half2*)(y + r0 + col) = __floats2half2_rn(o[n][0] * inv0, o[n][1] * inv0);
        *(__half2*)(y + r1 + col) = __floats2half2_rn(o[n][2] * inv1, o[n][3] * inv1);
    }
}

// ---------------- launch ----------------------------------------------------
template <typename T>
static T* symaddr(const void* sym) {
    void* p = nullptr;
    cudaGetSymbolAddress(&p, sym);
    return (T*)p;
}

extern "C" void kernel_launch(void* const* d_in, const int* in_sizes, int n_in,
                              void* d_out, int out_size) {
    const float* x      = (const float*)d_in[0];
    const float* ln1_w  = (const float*)d_in[1];
    const float* ln1_b  = (const float*)d_in[2];
    const float* qkv_w  = (const float*)d_in[3];
    const float* qkv_b  = (const float*)d_in[4];
    const float* out_w  = (const float*)d_in[5];
    const float* out_b  = (const float*)d_in[6];
    const float* ln2_w  = (const float*)d_in[7];
    const float* ln2_b  = (const float*)d_in[8];
    const float* mlp_w1 = (const float*)d_in[9];
    const float* mlp_b1 = (const float*)d_in[10];
    const float* mlp_w2 = (const float*)d_in[11];
    const float* mlp_b2 = (const float*)d_in[12];
    float* out = (float*)d_out;

    float*  x1   = symaddr<float>(g_x1);
    __half* qkvh = symaddr<__half>(g_qkv_h);
    __half* xlnh = symaddr<__half>(g_xln_h);
    __half* yh   = symaddr<__half>(g_y_h);
    __half* hh   = symaddr<__half>(g_h_h);
    __half* acth = symaddr<__half>(g_act_h);
    __half* wqh  = symaddr<__half>(g_wq_h);
    __half* woh  = symaddr<__half>(g_wo_h);
    __half* w1h  = symaddr<__half>(g_w1_h);
    __half* w2h  = symaddr<__half>(g_w2_h);

    cudaFuncSetAttribute(gemm_h<0,1>, cudaFuncAttributeMaxDynamicSharedMemorySize, GEMM_SMEM);
    cudaFuncSetAttribute(gemm_h<1,1>, cudaFuncAttributeMaxDynamicSharedMemorySize, GEMM_SMEM);
    cudaFuncSetAttribute(gemm_h<2,0>, cudaFuncAttributeMaxDynamicSharedMemorySize, GEMM_SMEM);

    // 0. weights -> half (2 float4 per thread for MLP)
    f2h_kernel<<<(D3 * DMODEL / 8 + 255) / 256, 256>>>((const float4*)qkv_w, (__half2*)wqh, D3 * DMODEL / 4);
    f2h_kernel<<<(DMODEL * DMODEL / 8 + 255) / 256, 256>>>((const float4*)out_w, (__half2*)woh, DMODEL * DMODEL / 4);
    f2h_kernel<<<(DFF * DMODEL / 8 + 255) / 256, 256>>>((const float4*)mlp_w1, (__half2*)w1h, DFF * DMODEL / 4);
    f2h_kernel<<<(DMODEL * DFF / 8 + 255) / 256, 256>>>((const float4*)mlp_w2, (__half2*)w2h, DMODEL * DFF / 4);

    // 1. LN1 -> half
    ln_kernel<<<MROWS, 256>>>(x, ln1_w, ln1_b, xlnh);
    // 2. QKV projection -> half qkv
    gemm_h<0,1><<<dim3(D3 / 128, MROWS / 128), 256, GEMM_SMEM>>>(xlnh, wqh, qkv_b, nullptr, nullptr, qkvh, D3, DMODEL);
    // 3. causal attention (fp16 mma, pipelined) -> half y
    attn_h<<<dim3(TSEQ / 64, NHEAD, 2), 128>>>(qkvh, yh);
    // 4. out projection + residual -> fp32 x1
    gemm_h<2,0><<<dim3(DMODEL / 128, MROWS / 128), 256, GEMM_SMEM>>>(yh, woh, out_b, x, x1, nullptr, DMODEL, DMODEL);
    // 5. LN2 -> half
    ln_kernel<<<MROWS, 256>>>(x1, ln2_w, ln2_b, hh);
    // 6. MLP up + exact GELU -> half act
    gemm_h<1,1><<<dim3(DFF / 128, MROWS / 128), 256, GEMM_SMEM>>>(hh, w1h, mlp_b1, nullptr, nullptr, acth, DFF, DMODEL);
    // 7. MLP down + residual -> fp32 output
    gemm_h<2,0><<<dim3(DMODEL / 128, MROWS / 128), 256, GEMM_SMEM>>>(acth, w2h, mlp_b2, x1, out, nullptr, DMODEL, DFF);
}